// round 1
// baseline (speedup 1.0000x reference)
#include <cuda_runtime.h>

#define BB 2
#define SS 4096
#define HH 2048
#define DD2 1024
#define NR (BB*SS)            // 8192 rows
#define NH (NR*HH)            // 16,777,216 elements per tensor
#define ATT_SCALE 0.125f

// Scratch (allocation-free rule: __device__ globals)
__device__ float g_q[NH];            // q pre-rope      (64 MB)
__device__ float g_qr[NH];           // q post-rope     (64 MB)
__device__ float g_tmp[NH];          // k pre-rope, then ctx (64 MB)
__device__ float g_scores[(size_t)BB*SS*SS];  // attention scores (128 MB)

// ---------------------------------------------------------------------------
// Generic fp32 tiled GEMM.
//   TRANSB=true :  C[m,n] = alpha * sum_k A[m*K+k] * B[n*K+k]   (NT)
//   TRANSB=false:  C[m,n] = alpha * sum_k A[m*K+k] * B[k*N+n]   (NN)
// BM=BN=128, BK=8, 256 threads, 8x8 per thread. All dims multiples of 128.
// ---------------------------------------------------------------------------
template<bool TRANSB>
__global__ __launch_bounds__(256)
void sgemm_kernel(const float* __restrict__ A, const float* __restrict__ Bm,
                  float* __restrict__ C, int M, int N, int K,
                  long strideA, long strideB, long strideC, float alpha)
{
    A  += (long)blockIdx.z * strideA;
    Bm += (long)blockIdx.z * strideB;
    C  += (long)blockIdx.z * strideC;

    __shared__ float As[8][128];
    __shared__ float Bs[8][128];

    const int tid = threadIdx.x;
    const int m0 = blockIdx.y * 128;
    const int n0 = blockIdx.x * 128;

    const int lrow = tid >> 1;          // 0..127
    const int lcol = (tid & 1) * 4;     // 0 or 4

    const int ty = tid >> 4;            // 0..15
    const int tx = tid & 15;            // 0..15

    float acc[8][8];
    #pragma unroll
    for (int i = 0; i < 8; i++)
        #pragma unroll
        for (int j = 0; j < 8; j++) acc[i][j] = 0.f;

    for (int k0 = 0; k0 < K; k0 += 8) {
        // global loads into registers
        float4 av = *(const float4*)&A[(long)(m0 + lrow) * K + k0 + lcol];
        float4 bv;
        if (TRANSB) {
            bv = *(const float4*)&Bm[(long)(n0 + lrow) * K + k0 + lcol];
        } else {
            bv = *(const float4*)&Bm[(long)(k0 + (tid >> 5)) * N + n0 + ((tid & 31) << 2)];
        }

        __syncthreads();   // previous tile's compute must finish before overwrite

        As[lcol + 0][lrow] = av.x;
        As[lcol + 1][lrow] = av.y;
        As[lcol + 2][lrow] = av.z;
        As[lcol + 3][lrow] = av.w;
        if (TRANSB) {
            Bs[lcol + 0][lrow] = bv.x;
            Bs[lcol + 1][lrow] = bv.y;
            Bs[lcol + 2][lrow] = bv.z;
            Bs[lcol + 3][lrow] = bv.w;
        } else {
            *(float4*)&Bs[tid >> 5][(tid & 31) << 2] = bv;
        }

        __syncthreads();

        #pragma unroll
        for (int kk = 0; kk < 8; kk++) {
            float a[8], b[8];
            #pragma unroll
            for (int i = 0; i < 8; i++) a[i] = As[kk][ty * 8 + i];
            #pragma unroll
            for (int j = 0; j < 8; j++) b[j] = Bs[kk][tx * 8 + j];
            #pragma unroll
            for (int i = 0; i < 8; i++)
                #pragma unroll
                for (int j = 0; j < 8; j++)
                    acc[i][j] = fmaf(a[i], b[j], acc[i][j]);
        }
    }

    #pragma unroll
    for (int i = 0; i < 8; i++) {
        long crow = (long)(m0 + ty * 8 + i) * N + n0 + tx * 8;
        float4 c0 = make_float4(alpha*acc[i][0], alpha*acc[i][1], alpha*acc[i][2], alpha*acc[i][3]);
        float4 c1 = make_float4(alpha*acc[i][4], alpha*acc[i][5], alpha*acc[i][6], alpha*acc[i][7]);
        *(float4*)&C[crow]     = c0;
        *(float4*)&C[crow + 4] = c1;
    }
}

// ---------------------------------------------------------------------------
// RoPE: out[row][2j] = x[row][j]*cos - x[row][j+D2]*sin
//       out[row][2j+1] = x[row][j]*sin + x[row][j+D2]*cos
// ---------------------------------------------------------------------------
__global__ __launch_bounds__(256)
void rope_kernel(const float* __restrict__ x, const float* __restrict__ fcos,
                 const float* __restrict__ fsin, float* __restrict__ out)
{
    long idx = (long)blockIdx.x * blockDim.x + threadIdx.x;  // NR*DD2 total
    if (idx >= (long)NR * DD2) return;
    int row = (int)(idx >> 10);        // idx / DD2
    int j   = (int)(idx & (DD2 - 1));
    int s   = row & (SS - 1);          // position within sequence
    float c  = fcos[(long)s * DD2 + j];
    float sn = fsin[(long)s * DD2 + j];
    float xr = x[(long)row * HH + j];
    float xi = x[(long)row * HH + j + DD2];
    float2 o = make_float2(xr * c - xi * sn, xr * sn + xi * c);
    ((float2*)out)[(long)row * DD2 + j] = o;
}

// ---------------------------------------------------------------------------
// Row softmax over SS=4096 elements. One block (256 threads) per row.
// ---------------------------------------------------------------------------
__global__ __launch_bounds__(256)
void softmax_kernel(float* __restrict__ sc)
{
    float* p = sc + (size_t)blockIdx.x * SS;
    const int tid = threadIdx.x;

    float4 v[4];
    float lmax = -3.0e38f;
    #pragma unroll
    for (int i = 0; i < 4; i++) {
        v[i] = ((float4*)p)[tid + i * 256];
        lmax = fmaxf(lmax, fmaxf(fmaxf(v[i].x, v[i].y), fmaxf(v[i].z, v[i].w)));
    }

    __shared__ float redmax[8];
    __shared__ float redsum[8];
    #pragma unroll
    for (int o = 16; o > 0; o >>= 1)
        lmax = fmaxf(lmax, __shfl_xor_sync(0xffffffffu, lmax, o));
    if ((tid & 31) == 0) redmax[tid >> 5] = lmax;
    __syncthreads();
    float bmax = redmax[0];
    #pragma unroll
    for (int w = 1; w < 8; w++) bmax = fmaxf(bmax, redmax[w]);

    float lsum = 0.f;
    #pragma unroll
    for (int i = 0; i < 4; i++) {
        v[i].x = __expf(v[i].x - bmax);
        v[i].y = __expf(v[i].y - bmax);
        v[i].z = __expf(v[i].z - bmax);
        v[i].w = __expf(v[i].w - bmax);
        lsum += v[i].x + v[i].y + v[i].z + v[i].w;
    }
    #pragma unroll
    for (int o = 16; o > 0; o >>= 1)
        lsum += __shfl_xor_sync(0xffffffffu, lsum, o);
    if ((tid & 31) == 0) redsum[tid >> 5] = lsum;
    __syncthreads();
    float bsum = 0.f;
    #pragma unroll
    for (int w = 0; w < 8; w++) bsum += redsum[w];
    float rinv = 1.f / bsum;

    #pragma unroll
    for (int i = 0; i < 4; i++) {
        v[i].x *= rinv; v[i].y *= rinv; v[i].z *= rinv; v[i].w *= rinv;
        ((float4*)p)[tid + i * 256] = v[i];
    }
}

// ---------------------------------------------------------------------------
extern "C" void kernel_launch(void* const* d_in, const int* in_sizes, int n_in,
                              void* d_out, int out_size)
{
    (void)in_sizes; (void)n_in; (void)out_size;
    const float* hs   = (const float*)d_in[0];
    const float* wq   = (const float*)d_in[1];
    const float* wk   = (const float*)d_in[2];
    const float* wv   = (const float*)d_in[3];
    const float* wo   = (const float*)d_in[4];
    const float* fcos = (const float*)d_in[5];
    const float* fsin = (const float*)d_in[6];
    // d_in[7] = position_ids == arange(S); implied by row index.

    float* out      = (float*)d_out;           // output  [B,S,H]
    float* out_krot = out + (long)NH;          // k_rot   [B,S,H]
    float* out_v    = out + 2L * NH;           // v       [B,S,H]

    float *gq, *gqr, *gtmp, *gsc;
    cudaGetSymbolAddress((void**)&gq,   g_q);
    cudaGetSymbolAddress((void**)&gqr,  g_qr);
    cudaGetSymbolAddress((void**)&gtmp, g_tmp);
    cudaGetSymbolAddress((void**)&gsc,  g_scores);

    // 1) QKV projections (NT): [8192,2048] @ [2048,2048]^T
    dim3 gQKV(HH / 128, NR / 128, 1);
    sgemm_kernel<true><<<gQKV, 256>>>(hs, wq, gq,    NR, HH, HH, 0, 0, 0, 1.f);
    sgemm_kernel<true><<<gQKV, 256>>>(hs, wk, gtmp,  NR, HH, HH, 0, 0, 0, 1.f);
    sgemm_kernel<true><<<gQKV, 256>>>(hs, wv, out_v, NR, HH, HH, 0, 0, 0, 1.f);

    // 2) RoPE on q and k (k_rot goes straight to its output region)
    long ropeN = (long)NR * DD2;
    int ropeBlocks = (int)((ropeN + 255) / 256);
    rope_kernel<<<ropeBlocks, 256>>>(gq,   fcos, fsin, gqr);
    rope_kernel<<<ropeBlocks, 256>>>(gtmp, fcos, fsin, out_krot);

    // 3) scores = scale * Qr @ Kr^T  per batch (NT, batched via grid.z)
    dim3 gSc(SS / 128, SS / 128, BB);
    sgemm_kernel<true><<<gSc, 256>>>(gqr, out_krot, gsc, SS, SS, HH,
                                     (long)SS * HH, (long)SS * HH, (long)SS * SS,
                                     ATT_SCALE);

    // 4) softmax over rows
    softmax_kernel<<<NR, 256>>>(gsc);

    // 5) ctx = P @ V per batch (NN) -> reuse g_tmp
    dim3 gCtx(HH / 128, SS / 128, BB);
    sgemm_kernel<false><<<gCtx, 256>>>(gsc, out_v, gtmp, SS, HH, SS,
                                       (long)SS * SS, (long)SS * HH, (long)SS * HH,
                                       1.f);

    // 6) output projection (NT): [8192,2048] @ [2048,2048]^T
    sgemm_kernel<true><<<gQKV, 256>>>(gtmp, wo, out, NR, HH, HH, 0, 0, 0, 1.f);
}

// round 3
// speedup vs baseline: 4.1769x; 4.1769x over previous
#include <cuda_runtime.h>
#include <cuda_bf16.h>
#include <cstdint>

#define BB 2
#define SS 4096
#define HH 2048
#define DD2 1024
#define NR (BB*SS)            // 8192
#define NH ((long)NR*HH)      // 16,777,216
#define NSCORE ((long)BB*SS*SS)
#define ATT_SCALE 0.125f

// ---------------- scratch (__device__ globals; no allocs allowed) ----------
__device__ float g_q[NH];
__device__ float g_k[NH];
__device__ float g_qr[NH];
__device__ float g_ctx[NH];
__device__ float g_scores[NSCORE];

__device__ __nv_bfloat16 g_hs_h[NH],  g_hs_l[NH];
__device__ __nv_bfloat16 g_w_h[4L*HH*HH], g_w_l[4L*HH*HH];
__device__ __nv_bfloat16 g_qr_h[NH], g_qr_l[NH];
__device__ __nv_bfloat16 g_kr_h[NH], g_kr_l[NH];
__device__ __nv_bfloat16 g_p_h[NSCORE], g_p_l[NSCORE];
__device__ __nv_bfloat16 g_vt_h[NH], g_vt_l[NH];
__device__ __nv_bfloat16 g_cx_h[NH], g_cx_l[NH];

// ---------------- PTX helpers (base sm_103 ISA only) -----------------------
__device__ __forceinline__ uint32_t smem_u32(const void* p) {
    uint32_t a;
    asm("{ .reg .u64 t; cvta.to.shared.u64 t, %1; cvt.u32.u64 %0, t; }" : "=r"(a) : "l"(p));
    return a;
}
#define CP_COMMIT()  asm volatile("cp.async.commit_group;" ::: "memory")
#define CP_WAIT(n)   asm volatile("cp.async.wait_group %0;" :: "n"(n) : "memory")

__device__ __forceinline__ void cp16(uint32_t dst, const void* src) {
    asm volatile("cp.async.cg.shared.global [%0], [%1], 16;"
                 :: "r"(dst), "l"(__cvta_generic_to_global(src)) : "memory");
}
__device__ __forceinline__ void ldsm_x4(uint32_t addr, uint32_t* r) {
    asm volatile("ldmatrix.sync.aligned.m8n8.x4.shared.b16 {%0,%1,%2,%3}, [%4];"
        : "=r"(r[0]), "=r"(r[1]), "=r"(r[2]), "=r"(r[3]) : "r"(addr));
}
__device__ __forceinline__ void mma16816(float* d, const uint32_t* a, const uint32_t* b) {
    asm volatile("mma.sync.aligned.m16n8k16.row.col.f32.bf16.bf16.f32 "
        "{%0,%1,%2,%3}, {%4,%5,%6,%7}, {%8,%9}, {%0,%1,%2,%3};"
        : "+f"(d[0]), "+f"(d[1]), "+f"(d[2]), "+f"(d[3])
        : "r"(a[0]), "r"(a[1]), "r"(a[2]), "r"(a[3]), "r"(b[0]), "r"(b[1]));
}

// SMEM tile layout: [128 rows][32 bf16] = 64B/row = 4 chunks of 16B.
// Swizzle: chunk' = chunk ^ ((row>>1)&3)  -> conflict-free cp.async stores
// and conflict-free ldmatrix (8 consecutive rows hit 8 distinct 16B phases).
__device__ __forceinline__ uint32_t swz(uint32_t row, uint32_t chunk) {
    return row * 64u + ((chunk ^ ((row >> 1) & 3u)) << 4);
}

// ---------------- bf16x3 HMMA GEMM: C = alpha * A[M,K] * B[N,K]^T ----------
// BM=BN=128, BK=32, 256 threads, 4-stage cp.async pipeline.
#define PART_BYTES 8192                 // 128*32*2
#define STAGE_BYTES (4*PART_BYTES)      // Ahi,Alo,Bhi,Blo
#define GEMM_SMEM (4*STAGE_BYTES)       // 128 KB

__global__ __launch_bounds__(256, 1)
void gemm_bf16x3(const __nv_bfloat16* __restrict__ Ahi, const __nv_bfloat16* __restrict__ Alo,
                 const __nv_bfloat16* __restrict__ Bhi, const __nv_bfloat16* __restrict__ Blo,
                 float* __restrict__ C, int M, int N, int K,
                 long sA, long sB, long sC, float alpha)
{
    extern __shared__ char smem[];
    const uint32_t sbase = smem_u32(smem);
    const int tid = threadIdx.x;
    Ahi += (long)blockIdx.z * sA;  Alo += (long)blockIdx.z * sA;
    Bhi += (long)blockIdx.z * sB;  Blo += (long)blockIdx.z * sB;
    C   += (long)blockIdx.z * sC;
    const int m0 = blockIdx.y * 128;
    const int n0 = blockIdx.x * 128;

    // ---- loader setup: thread -> (row, 2 chunks) ----
    const int lrow  = tid >> 1;
    const int cbase = (tid & 1) * 2;
    const __nv_bfloat16* pAh = Ahi + (long)(m0 + lrow) * K;
    const __nv_bfloat16* pAl = Alo + (long)(m0 + lrow) * K;
    const __nv_bfloat16* pBh = Bhi + (long)(n0 + lrow) * K;
    const __nv_bfloat16* pBl = Blo + (long)(n0 + lrow) * K;
    const uint32_t so0 = swz(lrow, cbase + 0);
    const uint32_t so1 = swz(lrow, cbase + 1);

    auto load_chunk = [&](int j, int slot) {
        uint32_t st = sbase + (uint32_t)slot * STAGE_BYTES;
        long k0 = (long)j * 32 + (long)cbase * 8;
        cp16(st + 0*PART_BYTES + so0, pAh + k0);
        cp16(st + 0*PART_BYTES + so1, pAh + k0 + 8);
        cp16(st + 1*PART_BYTES + so0, pAl + k0);
        cp16(st + 1*PART_BYTES + so1, pAl + k0 + 8);
        cp16(st + 2*PART_BYTES + so0, pBh + k0);
        cp16(st + 2*PART_BYTES + so1, pBh + k0 + 8);
        cp16(st + 3*PART_BYTES + so0, pBl + k0);
        cp16(st + 3*PART_BYTES + so1, pBl + k0 + 8);
    };

    // ---- compute setup ----
    const int lane = tid & 31;
    const int wid  = tid >> 5;
    const int wm   = wid & 3;        // M: wm*32
    const int wn   = wid >> 2;       // N: wn*64
    const int g    = lane >> 3;
    const int l7   = lane & 7;

    // A ldmatrix lane mapping (x4 -> a0..a3 of m16k16)
    uint32_t aro[2], asz[2];
    #pragma unroll
    for (int mt = 0; mt < 2; mt++) {
        uint32_t r = wm * 32 + mt * 16 + ((g & 1) << 3) + l7;
        aro[mt] = r * 64u; asz[mt] = (r >> 1) & 3u;
    }
    const uint32_t cbA = (uint32_t)(g >> 1);
    // B ldmatrix lane mapping (x4 -> two n8k16 frags)
    uint32_t bro[4], bsz[4];
    #pragma unroll
    for (int np = 0; np < 4; np++) {
        uint32_t r = wn * 64 + np * 16 + ((g >> 1) << 3) + l7;
        bro[np] = r * 64u; bsz[np] = (r >> 1) & 3u;
    }
    const uint32_t cbB = (uint32_t)(g & 1);

    float acc[2][8][4];
    #pragma unroll
    for (int mt = 0; mt < 2; mt++)
        #pragma unroll
        for (int nt = 0; nt < 8; nt++)
            #pragma unroll
            for (int i = 0; i < 4; i++) acc[mt][nt][i] = 0.f;

    const int nch = K / 32;
    // prologue: stages 0..2
    load_chunk(0, 0); CP_COMMIT();
    load_chunk(1, 1); CP_COMMIT();
    load_chunk(2, 2); CP_COMMIT();

    for (int i = 0; i < nch; i++) {
        CP_WAIT(2);
        __syncthreads();
        if (i + 3 < nch) load_chunk(i + 3, (i + 3) & 3);
        CP_COMMIT();

        uint32_t st = sbase + (uint32_t)(i & 3) * STAGE_BYTES;
        #pragma unroll
        for (int ks = 0; ks < 2; ks++) {
            uint32_t ah[2][4], al[2][4], bh[4][4], bl[4][4];
            #pragma unroll
            for (int mt = 0; mt < 2; mt++) {
                uint32_t off = aro[mt] + ((((uint32_t)(ks << 1) + cbA) ^ asz[mt]) << 4);
                ldsm_x4(st + 0*PART_BYTES + off, ah[mt]);
                ldsm_x4(st + 1*PART_BYTES + off, al[mt]);
            }
            #pragma unroll
            for (int np = 0; np < 4; np++) {
                uint32_t off = bro[np] + ((((uint32_t)(ks << 1) + cbB) ^ bsz[np]) << 4);
                ldsm_x4(st + 2*PART_BYTES + off, bh[np]);
                ldsm_x4(st + 3*PART_BYTES + off, bl[np]);
            }
            #pragma unroll
            for (int mt = 0; mt < 2; mt++)
                #pragma unroll
                for (int nt = 0; nt < 8; nt++) {
                    const uint32_t* bhp = &bh[nt >> 1][(nt & 1) * 2];
                    const uint32_t* blp = &bl[nt >> 1][(nt & 1) * 2];
                    mma16816(acc[mt][nt], ah[mt], bhp);
                    mma16816(acc[mt][nt], ah[mt], blp);
                    mma16816(acc[mt][nt], al[mt], bhp);
                }
        }
    }

    // ---- epilogue ----
    #pragma unroll
    for (int mt = 0; mt < 2; mt++)
        #pragma unroll
        for (int nt = 0; nt < 8; nt++) {
            int r0 = m0 + wm * 32 + mt * 16 + (lane >> 2);
            int c0 = n0 + wn * 64 + nt * 8 + (lane & 3) * 2;
            float2 v0 = make_float2(alpha * acc[mt][nt][0], alpha * acc[mt][nt][1]);
            float2 v1 = make_float2(alpha * acc[mt][nt][2], alpha * acc[mt][nt][3]);
            *(float2*)&C[(long)r0 * N + c0]       = v0;
            *(float2*)&C[(long)(r0 + 8) * N + c0] = v1;
        }
}

// ---------------- split: x -> (bf16 hi, bf16 lo) ---------------------------
__global__ __launch_bounds__(256)
void split_kernel(const float* __restrict__ x, __nv_bfloat16* __restrict__ hi,
                  __nv_bfloat16* __restrict__ lo, long n)
{
    long i = ((long)blockIdx.x * 256 + threadIdx.x) * 4;
    if (i >= n) return;
    float4 v = *(const float4*)&x[i];
    __nv_bfloat16 h0 = __float2bfloat16(v.x), h1 = __float2bfloat16(v.y);
    __nv_bfloat16 h2 = __float2bfloat16(v.z), h3 = __float2bfloat16(v.w);
    __nv_bfloat16 l0 = __float2bfloat16(v.x - __bfloat162float(h0));
    __nv_bfloat16 l1 = __float2bfloat16(v.y - __bfloat162float(h1));
    __nv_bfloat16 l2 = __float2bfloat16(v.z - __bfloat162float(h2));
    __nv_bfloat16 l3 = __float2bfloat16(v.w - __bfloat162float(h3));
    ((__nv_bfloat162*)&hi[i])[0] = __nv_bfloat162(h0, h1);
    ((__nv_bfloat162*)&hi[i])[1] = __nv_bfloat162(h2, h3);
    ((__nv_bfloat162*)&lo[i])[0] = __nv_bfloat162(l0, l1);
    ((__nv_bfloat162*)&lo[i])[1] = __nv_bfloat162(l2, l3);
}

// ---------------- transpose + split: V[b][s][h] -> Vt[b][h][s] -------------
__global__ __launch_bounds__(256)
void transpose_split_kernel(const float* __restrict__ V, __nv_bfloat16* __restrict__ hi,
                            __nv_bfloat16* __restrict__ lo)
{
    __shared__ float t[32][33];
    int b = blockIdx.z;
    int s0 = blockIdx.x * 32, h0 = blockIdx.y * 32;
    const float* Vb = V + (long)b * SS * HH;
    #pragma unroll
    for (int r = 0; r < 4; r++)
        t[threadIdx.y + r * 8][threadIdx.x] =
            Vb[(long)(s0 + threadIdx.y + r * 8) * HH + h0 + threadIdx.x];
    __syncthreads();
    #pragma unroll
    for (int r = 0; r < 4; r++) {
        int h = h0 + threadIdx.y + r * 8;
        float v = t[threadIdx.x][threadIdx.y + r * 8];
        __nv_bfloat16 hh = __float2bfloat16(v);
        __nv_bfloat16 ll = __float2bfloat16(v - __bfloat162float(hh));
        long o = (long)b * HH * SS + (long)h * SS + s0 + threadIdx.x;
        hi[o] = hh; lo[o] = ll;
    }
}

// ---------------- RoPE ------------------------------------------------------
__global__ __launch_bounds__(256)
void rope_kernel(const float* __restrict__ x, const float* __restrict__ fcos,
                 const float* __restrict__ fsin, float* __restrict__ out)
{
    long idx = (long)blockIdx.x * blockDim.x + threadIdx.x;
    if (idx >= (long)NR * DD2) return;
    int row = (int)(idx >> 10);
    int j   = (int)(idx & (DD2 - 1));
    int s   = row & (SS - 1);
    float c  = fcos[(long)s * DD2 + j];
    float sn = fsin[(long)s * DD2 + j];
    float xr = x[(long)row * HH + j];
    float xi = x[(long)row * HH + j + DD2];
    ((float2*)out)[(long)row * DD2 + j] = make_float2(xr * c - xi * sn, xr * sn + xi * c);
}

// ---------------- softmax ---------------------------------------------------
__global__ __launch_bounds__(256)
void softmax_kernel(float* __restrict__ sc)
{
    float* p = sc + (size_t)blockIdx.x * SS;
    const int tid = threadIdx.x;
    float4 v[4];
    float lmax = -3.0e38f;
    #pragma unroll
    for (int i = 0; i < 4; i++) {
        v[i] = ((float4*)p)[tid + i * 256];
        lmax = fmaxf(lmax, fmaxf(fmaxf(v[i].x, v[i].y), fmaxf(v[i].z, v[i].w)));
    }
    __shared__ float redmax[8], redsum[8];
    #pragma unroll
    for (int o = 16; o > 0; o >>= 1) lmax = fmaxf(lmax, __shfl_xor_sync(~0u, lmax, o));
    if ((tid & 31) == 0) redmax[tid >> 5] = lmax;
    __syncthreads();
    float bmax = redmax[0];
    #pragma unroll
    for (int w = 1; w < 8; w++) bmax = fmaxf(bmax, redmax[w]);
    float lsum = 0.f;
    #pragma unroll
    for (int i = 0; i < 4; i++) {
        v[i].x = __expf(v[i].x - bmax); v[i].y = __expf(v[i].y - bmax);
        v[i].z = __expf(v[i].z - bmax); v[i].w = __expf(v[i].w - bmax);
        lsum += v[i].x + v[i].y + v[i].z + v[i].w;
    }
    #pragma unroll
    for (int o = 16; o > 0; o >>= 1) lsum += __shfl_xor_sync(~0u, lsum, o);
    if ((tid & 31) == 0) redsum[tid >> 5] = lsum;
    __syncthreads();
    float bsum = 0.f;
    #pragma unroll
    for (int w = 0; w < 8; w++) bsum += redsum[w];
    float rinv = 1.f / bsum;
    #pragma unroll
    for (int i = 0; i < 4; i++) {
        v[i].x *= rinv; v[i].y *= rinv; v[i].z *= rinv; v[i].w *= rinv;
        ((float4*)p)[tid + i * 256] = v[i];
    }
}

// ---------------------------------------------------------------------------
extern "C" void kernel_launch(void* const* d_in, const int* in_sizes, int n_in,
                              void* d_out, int out_size)
{
    (void)in_sizes; (void)n_in; (void)out_size;
    const float* hs   = (const float*)d_in[0];
    const float* wq   = (const float*)d_in[1];
    const float* wk   = (const float*)d_in[2];
    const float* wv   = (const float*)d_in[3];
    const float* wo   = (const float*)d_in[4];
    const float* fcos = (const float*)d_in[5];
    const float* fsin = (const float*)d_in[6];

    float* out      = (float*)d_out;
    float* out_krot = out + NH;
    float* out_v    = out + 2 * NH;

    float *q, *k, *qr, *ctx, *sc;
    __nv_bfloat16 *hsh, *hsl, *wh, *wl, *qrh, *qrl, *krh, *krl, *ph, *pl, *vth, *vtl, *cxh, *cxl;
    cudaGetSymbolAddress((void**)&q,   g_q);
    cudaGetSymbolAddress((void**)&k,   g_k);
    cudaGetSymbolAddress((void**)&qr,  g_qr);
    cudaGetSymbolAddress((void**)&ctx, g_ctx);
    cudaGetSymbolAddress((void**)&sc,  g_scores);
    cudaGetSymbolAddress((void**)&hsh, g_hs_h);  cudaGetSymbolAddress((void**)&hsl, g_hs_l);
    cudaGetSymbolAddress((void**)&wh,  g_w_h);   cudaGetSymbolAddress((void**)&wl,  g_w_l);
    cudaGetSymbolAddress((void**)&qrh, g_qr_h);  cudaGetSymbolAddress((void**)&qrl, g_qr_l);
    cudaGetSymbolAddress((void**)&krh, g_kr_h);  cudaGetSymbolAddress((void**)&krl, g_kr_l);
    cudaGetSymbolAddress((void**)&ph,  g_p_h);   cudaGetSymbolAddress((void**)&pl,  g_p_l);
    cudaGetSymbolAddress((void**)&vth, g_vt_h);  cudaGetSymbolAddress((void**)&vtl, g_vt_l);
    cudaGetSymbolAddress((void**)&cxh, g_cx_h);  cudaGetSymbolAddress((void**)&cxl, g_cx_l);

    cudaFuncSetAttribute(gemm_bf16x3, cudaFuncAttributeMaxDynamicSharedMemorySize, GEMM_SMEM);

    const long WN = (long)HH * HH;
    auto SPLIT = [&](const float* x, __nv_bfloat16* h, __nv_bfloat16* l, long n) {
        split_kernel<<<(unsigned)((n / 4 + 255) / 256), 256>>>(x, h, l, n);
    };

    // 0) split inputs
    SPLIT(hs, hsh, hsl, NH);
    SPLIT(wq, wh + 0 * WN, wl + 0 * WN, WN);
    SPLIT(wk, wh + 1 * WN, wl + 1 * WN, WN);
    SPLIT(wv, wh + 2 * WN, wl + 2 * WN, WN);
    SPLIT(wo, wh + 3 * WN, wl + 3 * WN, WN);

    // 1) projections: [8192,2048] @ [2048,2048]^T
    dim3 gP(HH / 128, NR / 128, 1);
    gemm_bf16x3<<<gP, 256, GEMM_SMEM>>>(hsh, hsl, wh + 0 * WN, wl + 0 * WN, q,     NR, HH, HH, 0, 0, 0, 1.f);
    gemm_bf16x3<<<gP, 256, GEMM_SMEM>>>(hsh, hsl, wh + 1 * WN, wl + 1 * WN, k,     NR, HH, HH, 0, 0, 0, 1.f);
    gemm_bf16x3<<<gP, 256, GEMM_SMEM>>>(hsh, hsl, wh + 2 * WN, wl + 2 * WN, out_v, NR, HH, HH, 0, 0, 0, 1.f);

    // 2) RoPE
    int ropeBlocks = (int)(((long)NR * DD2 + 255) / 256);
    rope_kernel<<<ropeBlocks, 256>>>(q, fcos, fsin, qr);
    rope_kernel<<<ropeBlocks, 256>>>(k, fcos, fsin, out_krot);
    SPLIT(qr, qrh, qrl, NH);
    SPLIT(out_krot, krh, krl, NH);

    // 3) scores = 0.125 * Qr Kr^T  (batched)
    dim3 gS(SS / 128, SS / 128, BB);
    gemm_bf16x3<<<gS, 256, GEMM_SMEM>>>(qrh, qrl, krh, krl, sc, SS, SS, HH,
                                        (long)SS * HH, (long)SS * HH, (long)SS * SS, ATT_SCALE);

    // 4) softmax
    softmax_kernel<<<NR, 256>>>(sc);

    // 5) ctx = P @ V  (as NT with V^T)
    SPLIT(sc, ph, pl, NSCORE);
    dim3 gT(SS / 32, HH / 32, BB);
    transpose_split_kernel<<<gT, dim3(32, 8)>>>(out_v, vth, vtl);
    dim3 gC(HH / 128, SS / 128, BB);
    gemm_bf16x3<<<gC, 256, GEMM_SMEM>>>(ph, pl, vth, vtl, ctx, SS, HH, SS,
                                        (long)SS * SS, (long)HH * SS, (long)SS * HH, 1.f);

    // 6) output projection
    SPLIT(ctx, cxh, cxl, NH);
    gemm_bf16x3<<<gP, 256, GEMM_SMEM>>>(cxh, cxl, wh + 3 * WN, wl + 3 * WN, out, NR, HH, HH, 0, 0, 0, 1.f);
}

// round 4
// speedup vs baseline: 4.3615x; 1.0442x over previous
#include <cuda_runtime.h>
#include <cuda_bf16.h>
#include <cstdint>

#define BB 2
#define SS 4096
#define HH 2048
#define DD2 1024
#define NR (BB*SS)            // 8192
#define NH ((long)NR*HH)      // 16,777,216
#define NSCORE ((long)BB*SS*SS)
#define ATT_SCALE 0.125f

// ---------------- scratch (__device__ globals; no allocs allowed) ----------
__device__ float g_q[NH];
__device__ float g_k[NH];
__device__ float g_scores[NSCORE];

__device__ __nv_bfloat16 g_hs_h[NH],  g_hs_l[NH];
__device__ __nv_bfloat16 g_w_h[4L*HH*HH], g_w_l[4L*HH*HH];
__device__ __nv_bfloat16 g_qr_h[NH], g_qr_l[NH];
__device__ __nv_bfloat16 g_kr_h[NH], g_kr_l[NH];
__device__ __nv_bfloat16 g_p_h[NSCORE], g_p_l[NSCORE];
__device__ __nv_bfloat16 g_vt_h[NH], g_vt_l[NH];
__device__ __nv_bfloat16 g_cx_h[NH], g_cx_l[NH];

// ---------------- PTX helpers (base sm_103 ISA only) -----------------------
__device__ __forceinline__ uint32_t smem_u32(const void* p) {
    uint32_t a;
    asm("{ .reg .u64 t; cvta.to.shared.u64 t, %1; cvt.u32.u64 %0, t; }" : "=r"(a) : "l"(p));
    return a;
}
#define CP_COMMIT()  asm volatile("cp.async.commit_group;" ::: "memory")
#define CP_WAIT(n)   asm volatile("cp.async.wait_group %0;" :: "n"(n) : "memory")

__device__ __forceinline__ void cp16(uint32_t dst, const void* src) {
    asm volatile("cp.async.cg.shared.global [%0], [%1], 16;"
                 :: "r"(dst), "l"(__cvta_generic_to_global(src)) : "memory");
}
__device__ __forceinline__ void ldsm_x4(uint32_t addr, uint32_t* r) {
    asm volatile("ldmatrix.sync.aligned.m8n8.x4.shared.b16 {%0,%1,%2,%3}, [%4];"
        : "=r"(r[0]), "=r"(r[1]), "=r"(r[2]), "=r"(r[3]) : "r"(addr));
}
__device__ __forceinline__ void mma16816(float* d, const uint32_t* a, const uint32_t* b) {
    asm volatile("mma.sync.aligned.m16n8k16.row.col.f32.bf16.bf16.f32 "
        "{%0,%1,%2,%3}, {%4,%5,%6,%7}, {%8,%9}, {%0,%1,%2,%3};"
        : "+f"(d[0]), "+f"(d[1]), "+f"(d[2]), "+f"(d[3])
        : "r"(a[0]), "r"(a[1]), "r"(a[2]), "r"(a[3]), "r"(b[0]), "r"(b[1]));
}

// SMEM tile rows are 64B (32 bf16 = 4 16B chunks); chunk' = chunk ^ ((row>>1)&3)
__device__ __forceinline__ uint32_t swz(uint32_t row, uint32_t chunk) {
    return row * 64u + ((chunk ^ ((row >> 1) & 3u)) << 4);
}

// ---------------- bf16x3 HMMA GEMM: 128x256 tile, BK=32, 4 stages ----------
// MODE 0: C fp32 = alpha*acc.   MODE 1: (Ch,Cl) bf16 hi/lo split of acc.
#define OFF_AH 0
#define OFF_AL 8192
#define OFF_BH 16384
#define OFF_BL 32768
#define STAGE_BYTES 49152
#define GEMM_SMEM (4*STAGE_BYTES)       // 192 KB

template<int MODE>
__global__ __launch_bounds__(256, 1)
void gemm_bf16x3(const __nv_bfloat16* __restrict__ Ahi, const __nv_bfloat16* __restrict__ Alo,
                 const __nv_bfloat16* __restrict__ Bhi, const __nv_bfloat16* __restrict__ Blo,
                 float* __restrict__ C, __nv_bfloat16* __restrict__ Ch, __nv_bfloat16* __restrict__ Cl,
                 int M, int N, int K, long sA, long sB, long sC, float alpha)
{
    extern __shared__ char smem[];
    const uint32_t sbase = smem_u32(smem);
    const int tid = threadIdx.x;
    Ahi += (long)blockIdx.z * sA;  Alo += (long)blockIdx.z * sA;
    Bhi += (long)blockIdx.z * sB;  Blo += (long)blockIdx.z * sB;
    const int m0 = blockIdx.y * 128;
    const int n0 = blockIdx.x * 256;

    // ---- loader: row r = tid>>1 (A rows r; B rows r and r+128), 2 chunks ----
    const int r     = tid >> 1;
    const int cb    = (tid & 1) * 2;
    const __nv_bfloat16* pAh  = Ahi + (long)(m0 + r) * K;
    const __nv_bfloat16* pAl  = Alo + (long)(m0 + r) * K;
    const __nv_bfloat16* pBh0 = Bhi + (long)(n0 + r) * K;
    const __nv_bfloat16* pBl0 = Blo + (long)(n0 + r) * K;
    const __nv_bfloat16* pBh1 = Bhi + (long)(n0 + r + 128) * K;
    const __nv_bfloat16* pBl1 = Blo + (long)(n0 + r + 128) * K;
    const uint32_t so0 = swz((uint32_t)r, (uint32_t)cb);
    const uint32_t so1 = swz((uint32_t)r, (uint32_t)cb + 1);

    auto load_chunk = [&](int j, int slot) {
        uint32_t st = sbase + (uint32_t)slot * STAGE_BYTES;
        long k0 = (long)j * 32 + (long)cb * 8;
        cp16(st + OFF_AH + so0, pAh + k0);  cp16(st + OFF_AH + so1, pAh + k0 + 8);
        cp16(st + OFF_AL + so0, pAl + k0);  cp16(st + OFF_AL + so1, pAl + k0 + 8);
        cp16(st + OFF_BH + so0, pBh0 + k0); cp16(st + OFF_BH + so1, pBh0 + k0 + 8);
        cp16(st + OFF_BL + so0, pBl0 + k0); cp16(st + OFF_BL + so1, pBl0 + k0 + 8);
        cp16(st + OFF_BH + so0 + 8192, pBh1 + k0); cp16(st + OFF_BH + so1 + 8192, pBh1 + k0 + 8);
        cp16(st + OFF_BL + so0 + 8192, pBl1 + k0); cp16(st + OFF_BL + so1 + 8192, pBl1 + k0 + 8);
    };

    // ---- compute setup: warp grid 2(m) x 4(n), warp tile 64x64 ----
    const int lane = tid & 31;
    const int wid  = tid >> 5;
    const int wm   = wid & 1;
    const int wn   = wid >> 1;
    const int g    = lane >> 3;
    const int l7   = lane & 7;

    uint32_t aro[4], asz[4];
    #pragma unroll
    for (int mt = 0; mt < 4; mt++) {
        uint32_t rr = wm * 64 + mt * 16 + ((g & 1) << 3) + l7;
        aro[mt] = rr * 64u; asz[mt] = (rr >> 1) & 3u;
    }
    const uint32_t cbA = (uint32_t)(g >> 1);
    uint32_t bro[4], bsz[4];
    #pragma unroll
    for (int np = 0; np < 4; np++) {
        uint32_t rr = wn * 64 + np * 16 + ((g >> 1) << 3) + l7;
        bro[np] = rr * 64u; bsz[np] = (rr >> 1) & 3u;
    }
    const uint32_t cbB = (uint32_t)(g & 1);

    float acc[4][8][4];
    #pragma unroll
    for (int mt = 0; mt < 4; mt++)
        #pragma unroll
        for (int nt = 0; nt < 8; nt++)
            #pragma unroll
            for (int i = 0; i < 4; i++) acc[mt][nt][i] = 0.f;

    const int nch = K / 32;
    load_chunk(0, 0); CP_COMMIT();
    load_chunk(1, 1); CP_COMMIT();
    load_chunk(2, 2); CP_COMMIT();

    for (int i = 0; i < nch; i++) {
        CP_WAIT(2);
        __syncthreads();
        if (i + 3 < nch) load_chunk(i + 3, (i + 3) & 3);
        CP_COMMIT();

        uint32_t st = sbase + (uint32_t)(i & 3) * STAGE_BYTES;
        #pragma unroll
        for (int ks = 0; ks < 2; ks++) {
            uint32_t bh[4][4], bl[4][4];
            #pragma unroll
            for (int np = 0; np < 4; np++) {
                uint32_t off = bro[np] + ((((uint32_t)(ks << 1) + cbB) ^ bsz[np]) << 4);
                ldsm_x4(st + OFF_BH + off, bh[np]);
                ldsm_x4(st + OFF_BL + off, bl[np]);
            }
            #pragma unroll
            for (int mt = 0; mt < 4; mt++) {
                uint32_t ah[4], al[4];
                uint32_t off = aro[mt] + ((((uint32_t)(ks << 1) + cbA) ^ asz[mt]) << 4);
                ldsm_x4(st + OFF_AH + off, ah);
                ldsm_x4(st + OFF_AL + off, al);
                #pragma unroll
                for (int nt = 0; nt < 8; nt++) {
                    const uint32_t* bhp = &bh[nt >> 1][(nt & 1) * 2];
                    const uint32_t* blp = &bl[nt >> 1][(nt & 1) * 2];
                    mma16816(acc[mt][nt], ah, bhp);
                    mma16816(acc[mt][nt], ah, blp);
                    mma16816(acc[mt][nt], al, bhp);
                }
            }
        }
    }

    // ---- epilogue ----
    const long zC = (long)blockIdx.z * sC;
    #pragma unroll
    for (int mt = 0; mt < 4; mt++)
        #pragma unroll
        for (int nt = 0; nt < 8; nt++) {
            int r0 = m0 + wm * 64 + mt * 16 + (lane >> 2);
            int c0 = n0 + wn * 64 + nt * 8 + (lane & 3) * 2;
            float v0 = alpha * acc[mt][nt][0], v1 = alpha * acc[mt][nt][1];
            float v2 = alpha * acc[mt][nt][2], v3 = alpha * acc[mt][nt][3];
            if (MODE == 0) {
                *(float2*)&C[zC + (long)r0 * N + c0]       = make_float2(v0, v1);
                *(float2*)&C[zC + (long)(r0 + 8) * N + c0] = make_float2(v2, v3);
            } else {
                __nv_bfloat16 h0 = __float2bfloat16(v0), h1 = __float2bfloat16(v1);
                __nv_bfloat16 h2 = __float2bfloat16(v2), h3 = __float2bfloat16(v3);
                *(__nv_bfloat162*)&Ch[zC + (long)r0 * N + c0] = __nv_bfloat162(h0, h1);
                *(__nv_bfloat162*)&Ch[zC + (long)(r0 + 8) * N + c0] = __nv_bfloat162(h2, h3);
                __nv_bfloat16 q0 = __float2bfloat16(v0 - __bfloat162float(h0));
                __nv_bfloat16 q1 = __float2bfloat16(v1 - __bfloat162float(h1));
                __nv_bfloat16 q2 = __float2bfloat16(v2 - __bfloat162float(h2));
                __nv_bfloat16 q3 = __float2bfloat16(v3 - __bfloat162float(h3));
                *(__nv_bfloat162*)&Cl[zC + (long)r0 * N + c0] = __nv_bfloat162(q0, q1);
                *(__nv_bfloat162*)&Cl[zC + (long)(r0 + 8) * N + c0] = __nv_bfloat162(q2, q3);
            }
        }
}

// ---------------- split: x -> (bf16 hi, bf16 lo) ---------------------------
__global__ __launch_bounds__(256)
void split_kernel(const float* __restrict__ x, __nv_bfloat16* __restrict__ hi,
                  __nv_bfloat16* __restrict__ lo, long n)
{
    long i = ((long)blockIdx.x * 256 + threadIdx.x) * 4;
    if (i >= n) return;
    float4 v = *(const float4*)&x[i];
    __nv_bfloat16 h0 = __float2bfloat16(v.x), h1 = __float2bfloat16(v.y);
    __nv_bfloat16 h2 = __float2bfloat16(v.z), h3 = __float2bfloat16(v.w);
    __nv_bfloat16 l0 = __float2bfloat16(v.x - __bfloat162float(h0));
    __nv_bfloat16 l1 = __float2bfloat16(v.y - __bfloat162float(h1));
    __nv_bfloat16 l2 = __float2bfloat16(v.z - __bfloat162float(h2));
    __nv_bfloat16 l3 = __float2bfloat16(v.w - __bfloat162float(h3));
    ((__nv_bfloat162*)&hi[i])[0] = __nv_bfloat162(h0, h1);
    ((__nv_bfloat162*)&hi[i])[1] = __nv_bfloat162(h2, h3);
    ((__nv_bfloat162*)&lo[i])[0] = __nv_bfloat162(l0, l1);
    ((__nv_bfloat162*)&lo[i])[1] = __nv_bfloat162(l2, l3);
}

// ---------------- transpose + split: V[b][s][h] -> Vt[b][h][s] -------------
__global__ __launch_bounds__(256)
void transpose_split_kernel(const float* __restrict__ V, __nv_bfloat16* __restrict__ hi,
                            __nv_bfloat16* __restrict__ lo)
{
    __shared__ float t[32][33];
    int b = blockIdx.z;
    int s0 = blockIdx.x * 32, h0 = blockIdx.y * 32;
    const float* Vb = V + (long)b * SS * HH;
    #pragma unroll
    for (int r = 0; r < 4; r++)
        t[threadIdx.y + r * 8][threadIdx.x] =
            Vb[(long)(s0 + threadIdx.y + r * 8) * HH + h0 + threadIdx.x];
    __syncthreads();
    #pragma unroll
    for (int r = 0; r < 4; r++) {
        int h = h0 + threadIdx.y + r * 8;
        float v = t[threadIdx.x][threadIdx.y + r * 8];
        __nv_bfloat16 hh = __float2bfloat16(v);
        __nv_bfloat16 ll = __float2bfloat16(v - __bfloat162float(hh));
        long o = (long)b * HH * SS + (long)h * SS + s0 + threadIdx.x;
        hi[o] = hh; lo[o] = ll;
    }
}

// ---------------- fused RoPE + split ---------------------------------------
// WRITE_F32=1 additionally writes rotated fp32 (for k_rot output).
template<int WRITE_F32>
__global__ __launch_bounds__(256)
void rope_split_kernel(const float* __restrict__ x, const float* __restrict__ fcos,
                       const float* __restrict__ fsin, float* __restrict__ outf,
                       __nv_bfloat16* __restrict__ hi, __nv_bfloat16* __restrict__ lo)
{
    long idx = (long)blockIdx.x * blockDim.x + threadIdx.x;
    if (idx >= (long)NR * DD2) return;
    int row = (int)(idx >> 10);
    int j   = (int)(idx & (DD2 - 1));
    int s   = row & (SS - 1);
    float c  = fcos[(long)s * DD2 + j];
    float sn = fsin[(long)s * DD2 + j];
    float xr = x[(long)row * HH + j];
    float xi = x[(long)row * HH + j + DD2];
    float o0 = xr * c - xi * sn;
    float o1 = xr * sn + xi * c;
    if (WRITE_F32)
        ((float2*)outf)[(long)row * DD2 + j] = make_float2(o0, o1);
    __nv_bfloat16 h0 = __float2bfloat16(o0), h1 = __float2bfloat16(o1);
    ((__nv_bfloat162*)hi)[(long)row * DD2 + j] = __nv_bfloat162(h0, h1);
    __nv_bfloat16 l0 = __float2bfloat16(o0 - __bfloat162float(h0));
    __nv_bfloat16 l1 = __float2bfloat16(o1 - __bfloat162float(h1));
    ((__nv_bfloat162*)lo)[(long)row * DD2 + j] = __nv_bfloat162(l0, l1);
}

// ---------------- fused softmax + split ------------------------------------
__global__ __launch_bounds__(256)
void softmax_split_kernel(const float* __restrict__ sc,
                          __nv_bfloat16* __restrict__ ph, __nv_bfloat16* __restrict__ pl)
{
    const float* p = sc + (size_t)blockIdx.x * SS;
    __nv_bfloat16* oh = ph + (size_t)blockIdx.x * SS;
    __nv_bfloat16* ol = pl + (size_t)blockIdx.x * SS;
    const int tid = threadIdx.x;
    float4 v[4];
    float lmax = -3.0e38f;
    #pragma unroll
    for (int i = 0; i < 4; i++) {
        v[i] = ((const float4*)p)[tid + i * 256];
        lmax = fmaxf(lmax, fmaxf(fmaxf(v[i].x, v[i].y), fmaxf(v[i].z, v[i].w)));
    }
    __shared__ float redmax[8], redsum[8];
    #pragma unroll
    for (int o = 16; o > 0; o >>= 1) lmax = fmaxf(lmax, __shfl_xor_sync(~0u, lmax, o));
    if ((tid & 31) == 0) redmax[tid >> 5] = lmax;
    __syncthreads();
    float bmax = redmax[0];
    #pragma unroll
    for (int w = 1; w < 8; w++) bmax = fmaxf(bmax, redmax[w]);
    float lsum = 0.f;
    #pragma unroll
    for (int i = 0; i < 4; i++) {
        v[i].x = __expf(v[i].x - bmax); v[i].y = __expf(v[i].y - bmax);
        v[i].z = __expf(v[i].z - bmax); v[i].w = __expf(v[i].w - bmax);
        lsum += v[i].x + v[i].y + v[i].z + v[i].w;
    }
    #pragma unroll
    for (int o = 16; o > 0; o >>= 1) lsum += __shfl_xor_sync(~0u, lsum, o);
    if ((tid & 31) == 0) redsum[tid >> 5] = lsum;
    __syncthreads();
    float bsum = 0.f;
    #pragma unroll
    for (int w = 0; w < 8; w++) bsum += redsum[w];
    float rinv = 1.f / bsum;
    #pragma unroll
    for (int i = 0; i < 4; i++) {
        float a0 = v[i].x * rinv, a1 = v[i].y * rinv, a2 = v[i].z * rinv, a3 = v[i].w * rinv;
        int base = (tid + i * 256) * 4;
        __nv_bfloat16 h0 = __float2bfloat16(a0), h1 = __float2bfloat16(a1);
        __nv_bfloat16 h2 = __float2bfloat16(a2), h3 = __float2bfloat16(a3);
        ((__nv_bfloat162*)&oh[base])[0] = __nv_bfloat162(h0, h1);
        ((__nv_bfloat162*)&oh[base])[1] = __nv_bfloat162(h2, h3);
        __nv_bfloat16 l0 = __float2bfloat16(a0 - __bfloat162float(h0));
        __nv_bfloat16 l1 = __float2bfloat16(a1 - __bfloat162float(h1));
        __nv_bfloat16 l2 = __float2bfloat16(a2 - __bfloat162float(h2));
        __nv_bfloat16 l3 = __float2bfloat16(a3 - __bfloat162float(h3));
        ((__nv_bfloat162*)&ol[base])[0] = __nv_bfloat162(l0, l1);
        ((__nv_bfloat162*)&ol[base])[1] = __nv_bfloat162(l2, l3);
    }
}

// ---------------------------------------------------------------------------
extern "C" void kernel_launch(void* const* d_in, const int* in_sizes, int n_in,
                              void* d_out, int out_size)
{
    (void)in_sizes; (void)n_in; (void)out_size;
    const float* hs   = (const float*)d_in[0];
    const float* wq   = (const float*)d_in[1];
    const float* wk   = (const float*)d_in[2];
    const float* wv   = (const float*)d_in[3];
    const float* wo   = (const float*)d_in[4];
    const float* fcos = (const float*)d_in[5];
    const float* fsin = (const float*)d_in[6];

    float* out      = (float*)d_out;
    float* out_krot = out + NH;
    float* out_v    = out + 2 * NH;

    float *q, *k, *sc;
    __nv_bfloat16 *hsh, *hsl, *wh, *wl, *qrh, *qrl, *krh, *krl, *ph, *pl, *vth, *vtl, *cxh, *cxl;
    cudaGetSymbolAddress((void**)&q,   g_q);
    cudaGetSymbolAddress((void**)&k,   g_k);
    cudaGetSymbolAddress((void**)&sc,  g_scores);
    cudaGetSymbolAddress((void**)&hsh, g_hs_h);  cudaGetSymbolAddress((void**)&hsl, g_hs_l);
    cudaGetSymbolAddress((void**)&wh,  g_w_h);   cudaGetSymbolAddress((void**)&wl,  g_w_l);
    cudaGetSymbolAddress((void**)&qrh, g_qr_h);  cudaGetSymbolAddress((void**)&qrl, g_qr_l);
    cudaGetSymbolAddress((void**)&krh, g_kr_h);  cudaGetSymbolAddress((void**)&krl, g_kr_l);
    cudaGetSymbolAddress((void**)&ph,  g_p_h);   cudaGetSymbolAddress((void**)&pl,  g_p_l);
    cudaGetSymbolAddress((void**)&vth, g_vt_h);  cudaGetSymbolAddress((void**)&vtl, g_vt_l);
    cudaGetSymbolAddress((void**)&cxh, g_cx_h);  cudaGetSymbolAddress((void**)&cxl, g_cx_l);

    cudaFuncSetAttribute(gemm_bf16x3<0>, cudaFuncAttributeMaxDynamicSharedMemorySize, GEMM_SMEM);
    cudaFuncSetAttribute(gemm_bf16x3<1>, cudaFuncAttributeMaxDynamicSharedMemorySize, GEMM_SMEM);

    const long WN = (long)HH * HH;
    auto SPLIT = [&](const float* x, __nv_bfloat16* h, __nv_bfloat16* l, long n) {
        split_kernel<<<(unsigned)((n / 4 + 255) / 256), 256>>>(x, h, l, n);
    };

    // 0) split inputs
    SPLIT(hs, hsh, hsl, NH);
    SPLIT(wq, wh + 0 * WN, wl + 0 * WN, WN);
    SPLIT(wk, wh + 1 * WN, wl + 1 * WN, WN);
    SPLIT(wv, wh + 2 * WN, wl + 2 * WN, WN);
    SPLIT(wo, wh + 3 * WN, wl + 3 * WN, WN);

    // 1) projections: [8192,2048] @ [2048,2048]^T
    dim3 gP(HH / 256, NR / 128, 1);
    gemm_bf16x3<0><<<gP, 256, GEMM_SMEM>>>(hsh, hsl, wh + 0 * WN, wl + 0 * WN, q,     nullptr, nullptr, NR, HH, HH, 0, 0, 0, 1.f);
    gemm_bf16x3<0><<<gP, 256, GEMM_SMEM>>>(hsh, hsl, wh + 1 * WN, wl + 1 * WN, k,     nullptr, nullptr, NR, HH, HH, 0, 0, 0, 1.f);
    gemm_bf16x3<0><<<gP, 256, GEMM_SMEM>>>(hsh, hsl, wh + 2 * WN, wl + 2 * WN, out_v, nullptr, nullptr, NR, HH, HH, 0, 0, 0, 1.f);

    // 2) fused RoPE + split
    int ropeBlocks = (int)(((long)NR * DD2 + 255) / 256);
    rope_split_kernel<0><<<ropeBlocks, 256>>>(q, fcos, fsin, nullptr,   qrh, qrl);
    rope_split_kernel<1><<<ropeBlocks, 256>>>(k, fcos, fsin, out_krot, krh, krl);

    // 3) scores = 0.125 * Qr Kr^T  (batched)
    dim3 gS(SS / 256, SS / 128, BB);
    gemm_bf16x3<0><<<gS, 256, GEMM_SMEM>>>(qrh, qrl, krh, krl, sc, nullptr, nullptr, SS, SS, HH,
                                           (long)SS * HH, (long)SS * HH, (long)SS * SS, ATT_SCALE);

    // 4) fused softmax + split -> P hi/lo
    softmax_split_kernel<<<NR, 256>>>(sc, ph, pl);

    // 5) V transpose + split
    dim3 gT(SS / 32, HH / 32, BB);
    transpose_split_kernel<<<gT, dim3(32, 8)>>>(out_v, vth, vtl);

    // 6) ctx = P @ V^T -> split epilogue directly to cx hi/lo
    dim3 gC(HH / 256, SS / 128, BB);
    gemm_bf16x3<1><<<gC, 256, GEMM_SMEM>>>(ph, pl, vth, vtl, nullptr, cxh, cxl, SS, HH, SS,
                                           (long)SS * SS, (long)HH * SS, (long)SS * HH, 1.f);

    // 7) output projection
    gemm_bf16x3<0><<<gP, 256, GEMM_SMEM>>>(cxh, cxl, wh + 3 * WN, wl + 3 * WN, out, nullptr, nullptr, NR, HH, HH, 0, 0, 0, 1.f);
}

// round 5
// speedup vs baseline: 4.3657x; 1.0010x over previous
#include <cuda_runtime.h>
#include <cuda_bf16.h>
#include <cstdint>

#define BB 2
#define SS 4096
#define HH 2048
#define DD2 1024
#define NR (BB*SS)            // 8192
#define NH ((long)NR*HH)      // 16,777,216
#define NSCORE ((long)BB*SS*SS)
#define ATT_SCALE 0.125f

// ---------------- scratch (__device__ globals; no allocs allowed) ----------
__device__ float g_q[NH];
__device__ float g_k[NH];
__device__ float g_scores[NSCORE];

__device__ __nv_bfloat16 g_hs_h[NH],  g_hs_l[NH];
__device__ __nv_bfloat16 g_w_h[4L*HH*HH], g_w_l[4L*HH*HH];
__device__ __nv_bfloat16 g_qr_h[NH], g_qr_l[NH];
__device__ __nv_bfloat16 g_kr_h[NH], g_kr_l[NH];
__device__ __nv_bfloat16 g_p_h[NSCORE], g_p_l[NSCORE];
__device__ __nv_bfloat16 g_vt_h[NH], g_vt_l[NH];
__device__ __nv_bfloat16 g_cx_h[NH], g_cx_l[NH];

// ---------------- PTX helpers (base sm_103 ISA only) -----------------------
__device__ __forceinline__ uint32_t smem_u32(const void* p) {
    uint32_t a;
    asm("{ .reg .u64 t; cvta.to.shared.u64 t, %1; cvt.u32.u64 %0, t; }" : "=r"(a) : "l"(p));
    return a;
}
#define CP_COMMIT()  asm volatile("cp.async.commit_group;" ::: "memory")
#define CP_WAIT(n)   asm volatile("cp.async.wait_group %0;" :: "n"(n) : "memory")

__device__ __forceinline__ void cp16(uint32_t dst, const void* src) {
    asm volatile("cp.async.cg.shared.global [%0], [%1], 16;"
                 :: "r"(dst), "l"(__cvta_generic_to_global(src)) : "memory");
}
__device__ __forceinline__ void ldsm_x4(uint32_t addr, uint32_t* r) {
    asm volatile("ldmatrix.sync.aligned.m8n8.x4.shared.b16 {%0,%1,%2,%3}, [%4];"
        : "=r"(r[0]), "=r"(r[1]), "=r"(r[2]), "=r"(r[3]) : "r"(addr));
}
__device__ __forceinline__ void mma16816(float* d, const uint32_t* a, const uint32_t* b) {
    asm volatile("mma.sync.aligned.m16n8k16.row.col.f32.bf16.bf16.f32 "
        "{%0,%1,%2,%3}, {%4,%5,%6,%7}, {%8,%9}, {%0,%1,%2,%3};"
        : "+f"(d[0]), "+f"(d[1]), "+f"(d[2]), "+f"(d[3])
        : "r"(a[0]), "r"(a[1]), "r"(a[2]), "r"(a[3]), "r"(b[0]), "r"(b[1]));
}

// SMEM tile rows are 64B (32 bf16 = 4 16B chunks); chunk' = chunk ^ ((row>>1)&3)
__device__ __forceinline__ uint32_t swz(uint32_t row, uint32_t chunk) {
    return row * 64u + ((chunk ^ ((row >> 1) & 3u)) << 4);
}

// ---------------- bf16x3 HMMA GEMM: 128x256 tile, BK=32, 4 stages ----------
// MODE 0: C fp32 = alpha*acc.   MODE 1: (Ch,Cl) bf16 hi/lo split of acc.
#define OFF_AH 0
#define OFF_AL 8192
#define OFF_BH 16384
#define OFF_BL 32768
#define STAGE_BYTES 49152
#define GEMM_SMEM (4*STAGE_BYTES)       // 192 KB

template<int MODE>
__global__ __launch_bounds__(256, 1)
void gemm_bf16x3(const __nv_bfloat16* __restrict__ Ahi, const __nv_bfloat16* __restrict__ Alo,
                 const __nv_bfloat16* __restrict__ Bhi, const __nv_bfloat16* __restrict__ Blo,
                 float* __restrict__ C, __nv_bfloat16* __restrict__ Ch, __nv_bfloat16* __restrict__ Cl,
                 int M, int N, int K, long sA, long sB, long sC, float alpha)
{
    extern __shared__ char smem[];
    const uint32_t sbase = smem_u32(smem);
    const int tid = threadIdx.x;
    Ahi += (long)blockIdx.z * sA;  Alo += (long)blockIdx.z * sA;
    Bhi += (long)blockIdx.z * sB;  Blo += (long)blockIdx.z * sB;
    const int m0 = blockIdx.y * 128;
    const int n0 = blockIdx.x * 256;

    // ---- loader: row r = tid>>1 (A rows r; B rows r and r+128), 2 chunks ----
    const int r     = tid >> 1;
    const int cb    = (tid & 1) * 2;
    const __nv_bfloat16* pAh  = Ahi + (long)(m0 + r) * K;
    const __nv_bfloat16* pAl  = Alo + (long)(m0 + r) * K;
    const __nv_bfloat16* pBh0 = Bhi + (long)(n0 + r) * K;
    const __nv_bfloat16* pBl0 = Blo + (long)(n0 + r) * K;
    const __nv_bfloat16* pBh1 = Bhi + (long)(n0 + r + 128) * K;
    const __nv_bfloat16* pBl1 = Blo + (long)(n0 + r + 128) * K;
    const uint32_t so0 = swz((uint32_t)r, (uint32_t)cb);
    const uint32_t so1 = swz((uint32_t)r, (uint32_t)cb + 1);

    auto load_chunk = [&](int j, int slot) {
        uint32_t st = sbase + (uint32_t)slot * STAGE_BYTES;
        long k0 = (long)j * 32 + (long)cb * 8;
        cp16(st + OFF_AH + so0, pAh + k0);  cp16(st + OFF_AH + so1, pAh + k0 + 8);
        cp16(st + OFF_AL + so0, pAl + k0);  cp16(st + OFF_AL + so1, pAl + k0 + 8);
        cp16(st + OFF_BH + so0, pBh0 + k0); cp16(st + OFF_BH + so1, pBh0 + k0 + 8);
        cp16(st + OFF_BL + so0, pBl0 + k0); cp16(st + OFF_BL + so1, pBl0 + k0 + 8);
        cp16(st + OFF_BH + so0 + 8192, pBh1 + k0); cp16(st + OFF_BH + so1 + 8192, pBh1 + k0 + 8);
        cp16(st + OFF_BL + so0 + 8192, pBl1 + k0); cp16(st + OFF_BL + so1 + 8192, pBl1 + k0 + 8);
    };

    // ---- compute setup: warp grid 2(m) x 4(n), warp tile 64x64 ----
    const int lane = tid & 31;
    const int wid  = tid >> 5;
    const int wm   = wid & 1;
    const int wn   = wid >> 1;
    const int g    = lane >> 3;
    const int l7   = lane & 7;

    uint32_t aro[4], asz[4];
    #pragma unroll
    for (int mt = 0; mt < 4; mt++) {
        uint32_t rr = wm * 64 + mt * 16 + ((g & 1) << 3) + l7;
        aro[mt] = rr * 64u; asz[mt] = (rr >> 1) & 3u;
    }
    const uint32_t cbA = (uint32_t)(g >> 1);
    uint32_t bro[4], bsz[4];
    #pragma unroll
    for (int np = 0; np < 4; np++) {
        uint32_t rr = wn * 64 + np * 16 + ((g >> 1) << 3) + l7;
        bro[np] = rr * 64u; bsz[np] = (rr >> 1) & 3u;
    }
    const uint32_t cbB = (uint32_t)(g & 1);

    float acc[4][8][4];
    #pragma unroll
    for (int mt = 0; mt < 4; mt++)
        #pragma unroll
        for (int nt = 0; nt < 8; nt++)
            #pragma unroll
            for (int i = 0; i < 4; i++) acc[mt][nt][i] = 0.f;

    const int nch = K / 32;
    load_chunk(0, 0); CP_COMMIT();
    load_chunk(1, 1); CP_COMMIT();
    load_chunk(2, 2); CP_COMMIT();

    for (int i = 0; i < nch; i++) {
        CP_WAIT(2);
        __syncthreads();
        if (i + 3 < nch) load_chunk(i + 3, (i + 3) & 3);
        CP_COMMIT();

        uint32_t st = sbase + (uint32_t)(i & 3) * STAGE_BYTES;
        #pragma unroll
        for (int ks = 0; ks < 2; ks++) {
            uint32_t bh[4][4], bl[4][4];
            #pragma unroll
            for (int np = 0; np < 4; np++) {
                uint32_t off = bro[np] + ((((uint32_t)(ks << 1) + cbB) ^ bsz[np]) << 4);
                ldsm_x4(st + OFF_BH + off, bh[np]);
                ldsm_x4(st + OFF_BL + off, bl[np]);
            }
            #pragma unroll
            for (int mt = 0; mt < 4; mt++) {
                uint32_t ah[4], al[4];
                uint32_t off = aro[mt] + ((((uint32_t)(ks << 1) + cbA) ^ asz[mt]) << 4);
                ldsm_x4(st + OFF_AH + off, ah);
                ldsm_x4(st + OFF_AL + off, al);
                // term-major: same-acc MMAs are 8 apart -> no RAW back-to-back
                #pragma unroll
                for (int nt = 0; nt < 8; nt++)
                    mma16816(acc[mt][nt], ah, &bh[nt >> 1][(nt & 1) * 2]);
                #pragma unroll
                for (int nt = 0; nt < 8; nt++)
                    mma16816(acc[mt][nt], ah, &bl[nt >> 1][(nt & 1) * 2]);
                #pragma unroll
                for (int nt = 0; nt < 8; nt++)
                    mma16816(acc[mt][nt], al, &bh[nt >> 1][(nt & 1) * 2]);
            }
        }
    }

    // ---- epilogue ----
    const long zC = (long)blockIdx.z * sC;
    #pragma unroll
    for (int mt = 0; mt < 4; mt++)
        #pragma unroll
        for (int nt = 0; nt < 8; nt++) {
            int r0 = m0 + wm * 64 + mt * 16 + (lane >> 2);
            int c0 = n0 + wn * 64 + nt * 8 + (lane & 3) * 2;
            float v0 = alpha * acc[mt][nt][0], v1 = alpha * acc[mt][nt][1];
            float v2 = alpha * acc[mt][nt][2], v3 = alpha * acc[mt][nt][3];
            if (MODE == 0) {
                *(float2*)&C[zC + (long)r0 * N + c0]       = make_float2(v0, v1);
                *(float2*)&C[zC + (long)(r0 + 8) * N + c0] = make_float2(v2, v3);
            } else {
                __nv_bfloat16 h0 = __float2bfloat16(v0), h1 = __float2bfloat16(v1);
                __nv_bfloat16 h2 = __float2bfloat16(v2), h3 = __float2bfloat16(v3);
                *(__nv_bfloat162*)&Ch[zC + (long)r0 * N + c0] = __nv_bfloat162(h0, h1);
                *(__nv_bfloat162*)&Ch[zC + (long)(r0 + 8) * N + c0] = __nv_bfloat162(h2, h3);
                __nv_bfloat16 q0 = __float2bfloat16(v0 - __bfloat162float(h0));
                __nv_bfloat16 q1 = __float2bfloat16(v1 - __bfloat162float(h1));
                __nv_bfloat16 q2 = __float2bfloat16(v2 - __bfloat162float(h2));
                __nv_bfloat16 q3 = __float2bfloat16(v3 - __bfloat162float(h3));
                *(__nv_bfloat162*)&Cl[zC + (long)r0 * N + c0] = __nv_bfloat162(q0, q1);
                *(__nv_bfloat162*)&Cl[zC + (long)(r0 + 8) * N + c0] = __nv_bfloat162(q2, q3);
            }
        }
}

// ---------------- split: x -> (bf16 hi, bf16 lo) ---------------------------
__global__ __launch_bounds__(256)
void split_kernel(const float* __restrict__ x, __nv_bfloat16* __restrict__ hi,
                  __nv_bfloat16* __restrict__ lo, long n)
{
    long i = ((long)blockIdx.x * 256 + threadIdx.x) * 4;
    if (i >= n) return;
    float4 v = *(const float4*)&x[i];
    __nv_bfloat16 h0 = __float2bfloat16(v.x), h1 = __float2bfloat16(v.y);
    __nv_bfloat16 h2 = __float2bfloat16(v.z), h3 = __float2bfloat16(v.w);
    __nv_bfloat16 l0 = __float2bfloat16(v.x - __bfloat162float(h0));
    __nv_bfloat16 l1 = __float2bfloat16(v.y - __bfloat162float(h1));
    __nv_bfloat16 l2 = __float2bfloat16(v.z - __bfloat162float(h2));
    __nv_bfloat16 l3 = __float2bfloat16(v.w - __bfloat162float(h3));
    ((__nv_bfloat162*)&hi[i])[0] = __nv_bfloat162(h0, h1);
    ((__nv_bfloat162*)&hi[i])[1] = __nv_bfloat162(h2, h3);
    ((__nv_bfloat162*)&lo[i])[0] = __nv_bfloat162(l0, l1);
    ((__nv_bfloat162*)&lo[i])[1] = __nv_bfloat162(l2, l3);
}

// ---------------- transpose + split: V[b][s][h] -> Vt[b][h][s] -------------
__global__ __launch_bounds__(256)
void transpose_split_kernel(const float* __restrict__ V, __nv_bfloat16* __restrict__ hi,
                            __nv_bfloat16* __restrict__ lo)
{
    __shared__ float t[32][33];
    int b = blockIdx.z;
    int s0 = blockIdx.x * 32, h0 = blockIdx.y * 32;
    const float* Vb = V + (long)b * SS * HH;
    #pragma unroll
    for (int r = 0; r < 4; r++)
        t[threadIdx.y + r * 8][threadIdx.x] =
            Vb[(long)(s0 + threadIdx.y + r * 8) * HH + h0 + threadIdx.x];
    __syncthreads();
    #pragma unroll
    for (int r = 0; r < 4; r++) {
        int h = h0 + threadIdx.y + r * 8;
        float v = t[threadIdx.x][threadIdx.y + r * 8];
        __nv_bfloat16 hh = __float2bfloat16(v);
        __nv_bfloat16 ll = __float2bfloat16(v - __bfloat162float(hh));
        long o = (long)b * HH * SS + (long)h * SS + s0 + threadIdx.x;
        hi[o] = hh; lo[o] = ll;
    }
}

// ---------------- fused RoPE + split ---------------------------------------
template<int WRITE_F32>
__global__ __launch_bounds__(256)
void rope_split_kernel(const float* __restrict__ x, const float* __restrict__ fcos,
                       const float* __restrict__ fsin, float* __restrict__ outf,
                       __nv_bfloat16* __restrict__ hi, __nv_bfloat16* __restrict__ lo)
{
    long idx = (long)blockIdx.x * blockDim.x + threadIdx.x;
    if (idx >= (long)NR * DD2) return;
    int row = (int)(idx >> 10);
    int j   = (int)(idx & (DD2 - 1));
    int s   = row & (SS - 1);
    float c  = fcos[(long)s * DD2 + j];
    float sn = fsin[(long)s * DD2 + j];
    float xr = x[(long)row * HH + j];
    float xi = x[(long)row * HH + j + DD2];
    float o0 = xr * c - xi * sn;
    float o1 = xr * sn + xi * c;
    if (WRITE_F32)
        ((float2*)outf)[(long)row * DD2 + j] = make_float2(o0, o1);
    __nv_bfloat16 h0 = __float2bfloat16(o0), h1 = __float2bfloat16(o1);
    ((__nv_bfloat162*)hi)[(long)row * DD2 + j] = __nv_bfloat162(h0, h1);
    __nv_bfloat16 l0 = __float2bfloat16(o0 - __bfloat162float(h0));
    __nv_bfloat16 l1 = __float2bfloat16(o1 - __bfloat162float(h1));
    ((__nv_bfloat162*)lo)[(long)row * DD2 + j] = __nv_bfloat162(l0, l1);
}

// ---------------- fused softmax + split ------------------------------------
__global__ __launch_bounds__(256)
void softmax_split_kernel(const float* __restrict__ sc,
                          __nv_bfloat16* __restrict__ ph, __nv_bfloat16* __restrict__ pl)
{
    const float* p = sc + (size_t)blockIdx.x * SS;
    __nv_bfloat16* oh = ph + (size_t)blockIdx.x * SS;
    __nv_bfloat16* ol = pl + (size_t)blockIdx.x * SS;
    const int tid = threadIdx.x;
    float4 v[4];
    float lmax = -3.0e38f;
    #pragma unroll
    for (int i = 0; i < 4; i++) {
        v[i] = ((const float4*)p)[tid + i * 256];
        lmax = fmaxf(lmax, fmaxf(fmaxf(v[i].x, v[i].y), fmaxf(v[i].z, v[i].w)));
    }
    __shared__ float redmax[8], redsum[8];
    #pragma unroll
    for (int o = 16; o > 0; o >>= 1) lmax = fmaxf(lmax, __shfl_xor_sync(~0u, lmax, o));
    if ((tid & 31) == 0) redmax[tid >> 5] = lmax;
    __syncthreads();
    float bmax = redmax[0];
    #pragma unroll
    for (int w = 1; w < 8; w++) bmax = fmaxf(bmax, redmax[w]);
    float lsum = 0.f;
    #pragma unroll
    for (int i = 0; i < 4; i++) {
        v[i].x = __expf(v[i].x - bmax); v[i].y = __expf(v[i].y - bmax);
        v[i].z = __expf(v[i].z - bmax); v[i].w = __expf(v[i].w - bmax);
        lsum += v[i].x + v[i].y + v[i].z + v[i].w;
    }
    #pragma unroll
    for (int o = 16; o > 0; o >>= 1) lsum += __shfl_xor_sync(~0u, lsum, o);
    if ((tid & 31) == 0) redsum[tid >> 5] = lsum;
    __syncthreads();
    float bsum = 0.f;
    #pragma unroll
    for (int w = 0; w < 8; w++) bsum += redsum[w];
    float rinv = 1.f / bsum;
    #pragma unroll
    for (int i = 0; i < 4; i++) {
        float a0 = v[i].x * rinv, a1 = v[i].y * rinv, a2 = v[i].z * rinv, a3 = v[i].w * rinv;
        int base = (tid + i * 256) * 4;
        __nv_bfloat16 h0 = __float2bfloat16(a0), h1 = __float2bfloat16(a1);
        __nv_bfloat16 h2 = __float2bfloat16(a2), h3 = __float2bfloat16(a3);
        ((__nv_bfloat162*)&oh[base])[0] = __nv_bfloat162(h0, h1);
        ((__nv_bfloat162*)&oh[base])[1] = __nv_bfloat162(h2, h3);
        __nv_bfloat16 l0 = __float2bfloat16(a0 - __bfloat162float(h0));
        __nv_bfloat16 l1 = __float2bfloat16(a1 - __bfloat162float(h1));
        __nv_bfloat16 l2 = __float2bfloat16(a2 - __bfloat162float(h2));
        __nv_bfloat16 l3 = __float2bfloat16(a3 - __bfloat162float(h3));
        ((__nv_bfloat162*)&ol[base])[0] = __nv_bfloat162(l0, l1);
        ((__nv_bfloat162*)&ol[base])[1] = __nv_bfloat162(l2, l3);
    }
}

// ---------------------------------------------------------------------------
extern "C" void kernel_launch(void* const* d_in, const int* in_sizes, int n_in,
                              void* d_out, int out_size)
{
    (void)in_sizes; (void)n_in; (void)out_size;
    const float* hs   = (const float*)d_in[0];
    const float* wq   = (const float*)d_in[1];
    const float* wk   = (const float*)d_in[2];
    const float* wv   = (const float*)d_in[3];
    const float* wo   = (const float*)d_in[4];
    const float* fcos = (const float*)d_in[5];
    const float* fsin = (const float*)d_in[6];

    float* out      = (float*)d_out;
    float* out_krot = out + NH;
    float* out_v    = out + 2 * NH;

    float *q, *k, *sc;
    __nv_bfloat16 *hsh, *hsl, *wh, *wl, *qrh, *qrl, *krh, *krl, *ph, *pl, *vth, *vtl, *cxh, *cxl;
    cudaGetSymbolAddress((void**)&q,   g_q);
    cudaGetSymbolAddress((void**)&k,   g_k);
    cudaGetSymbolAddress((void**)&sc,  g_scores);
    cudaGetSymbolAddress((void**)&hsh, g_hs_h);  cudaGetSymbolAddress((void**)&hsl, g_hs_l);
    cudaGetSymbolAddress((void**)&wh,  g_w_h);   cudaGetSymbolAddress((void**)&wl,  g_w_l);
    cudaGetSymbolAddress((void**)&qrh, g_qr_h);  cudaGetSymbolAddress((void**)&qrl, g_qr_l);
    cudaGetSymbolAddress((void**)&krh, g_kr_h);  cudaGetSymbolAddress((void**)&krl, g_kr_l);
    cudaGetSymbolAddress((void**)&ph,  g_p_h);   cudaGetSymbolAddress((void**)&pl,  g_p_l);
    cudaGetSymbolAddress((void**)&vth, g_vt_h);  cudaGetSymbolAddress((void**)&vtl, g_vt_l);
    cudaGetSymbolAddress((void**)&cxh, g_cx_h);  cudaGetSymbolAddress((void**)&cxl, g_cx_l);

    cudaFuncSetAttribute(gemm_bf16x3<0>, cudaFuncAttributeMaxDynamicSharedMemorySize, GEMM_SMEM);
    cudaFuncSetAttribute(gemm_bf16x3<1>, cudaFuncAttributeMaxDynamicSharedMemorySize, GEMM_SMEM);

    const long WN = (long)HH * HH;
    auto SPLIT = [&](const float* x, __nv_bfloat16* h, __nv_bfloat16* l, long n) {
        split_kernel<<<(unsigned)((n / 4 + 255) / 256), 256>>>(x, h, l, n);
    };

    // 0) split inputs
    SPLIT(hs, hsh, hsl, NH);
    SPLIT(wq, wh + 0 * WN, wl + 0 * WN, WN);
    SPLIT(wk, wh + 1 * WN, wl + 1 * WN, WN);
    SPLIT(wv, wh + 2 * WN, wl + 2 * WN, WN);
    SPLIT(wo, wh + 3 * WN, wl + 3 * WN, WN);

    // 1) projections: [8192,2048] @ [2048,2048]^T
    dim3 gP(HH / 256, NR / 128, 1);
    gemm_bf16x3<0><<<gP, 256, GEMM_SMEM>>>(hsh, hsl, wh + 0 * WN, wl + 0 * WN, q,     nullptr, nullptr, NR, HH, HH, 0, 0, 0, 1.f);
    gemm_bf16x3<0><<<gP, 256, GEMM_SMEM>>>(hsh, hsl, wh + 1 * WN, wl + 1 * WN, k,     nullptr, nullptr, NR, HH, HH, 0, 0, 0, 1.f);
    gemm_bf16x3<0><<<gP, 256, GEMM_SMEM>>>(hsh, hsl, wh + 2 * WN, wl + 2 * WN, out_v, nullptr, nullptr, NR, HH, HH, 0, 0, 0, 1.f);

    // 2) fused RoPE + split
    int ropeBlocks = (int)(((long)NR * DD2 + 255) / 256);
    rope_split_kernel<0><<<ropeBlocks, 256>>>(q, fcos, fsin, nullptr,   qrh, qrl);
    rope_split_kernel<1><<<ropeBlocks, 256>>>(k, fcos, fsin, out_krot, krh, krl);

    // 3) scores = 0.125 * Qr Kr^T  (batched)
    dim3 gS(SS / 256, SS / 128, BB);
    gemm_bf16x3<0><<<gS, 256, GEMM_SMEM>>>(qrh, qrl, krh, krl, sc, nullptr, nullptr, SS, SS, HH,
                                           (long)SS * HH, (long)SS * HH, (long)SS * SS, ATT_SCALE);

    // 4) fused softmax + split -> P hi/lo
    softmax_split_kernel<<<NR, 256>>>(sc, ph, pl);

    // 5) V transpose + split
    dim3 gT(SS / 32, HH / 32, BB);
    transpose_split_kernel<<<gT, dim3(32, 8)>>>(out_v, vth, vtl);

    // 6) ctx = P @ V^T -> split epilogue directly to cx hi/lo
    dim3 gC(HH / 256, SS / 128, BB);
    gemm_bf16x3<1><<<gC, 256, GEMM_SMEM>>>(ph, pl, vth, vtl, nullptr, cxh, cxl, SS, HH, SS,
                                           (long)SS * SS, (long)HH * SS, (long)SS * HH, 1.f);

    // 7) output projection
    gemm_bf16x3<0><<<gP, 256, GEMM_SMEM>>>(cxh, cxl, wh + 3 * WN, wl + 3 * WN, out, nullptr, nullptr, NR, HH, HH, 0, 0, 0, 1.f);
}

// round 6
// speedup vs baseline: 4.7325x; 1.0840x over previous
#include <cuda_runtime.h>
#include <cuda_bf16.h>
#include <cstdint>

#define BB 2
#define SS 4096
#define HH 2048
#define DD2 1024
#define NR (BB*SS)            // 8192
#define NH ((long)NR*HH)      // 16,777,216
#define NSCORE ((long)BB*SS*SS)
#define ATT_SCALE 0.125f

// ---------------- scratch (__device__ globals; no allocs allowed) ----------
__device__ float g_q[NH];
__device__ float g_k[NH];
__device__ float g_scores[NSCORE];

__device__ __nv_bfloat16 g_hs_h[NH],  g_hs_l[NH];
__device__ __nv_bfloat16 g_w_h[4L*HH*HH], g_w_l[4L*HH*HH];
__device__ __nv_bfloat16 g_qr_h[NH], g_qr_l[NH];
__device__ __nv_bfloat16 g_kr_h[NH], g_kr_l[NH];
__device__ __nv_bfloat16 g_p_h[NSCORE], g_p_l[NSCORE];
__device__ __nv_bfloat16 g_vt_h[NH], g_vt_l[NH];
__device__ __nv_bfloat16 g_cx_h[NH], g_cx_l[NH];

// ---------------- PTX helpers (base sm_103 ISA only) -----------------------
__device__ __forceinline__ uint32_t smem_u32(const void* p) {
    uint32_t a;
    asm("{ .reg .u64 t; cvta.to.shared.u64 t, %1; cvt.u32.u64 %0, t; }" : "=r"(a) : "l"(p));
    return a;
}
#define CP_COMMIT()  asm volatile("cp.async.commit_group;" ::: "memory")
#define CP_WAIT(n)   asm volatile("cp.async.wait_group %0;" :: "n"(n) : "memory")

__device__ __forceinline__ void cp16(uint32_t dst, const void* src) {
    asm volatile("cp.async.cg.shared.global [%0], [%1], 16;"
                 :: "r"(dst), "l"(__cvta_generic_to_global(src)) : "memory");
}
__device__ __forceinline__ void ldsm_x4(uint32_t addr, uint32_t* r) {
    asm volatile("ldmatrix.sync.aligned.m8n8.x4.shared.b16 {%0,%1,%2,%3}, [%4];"
        : "=r"(r[0]), "=r"(r[1]), "=r"(r[2]), "=r"(r[3]) : "r"(addr));
}
__device__ __forceinline__ void mma16816(float* d, const uint32_t* a, const uint32_t* b) {
    asm volatile("mma.sync.aligned.m16n8k16.row.col.f32.bf16.bf16.f32 "
        "{%0,%1,%2,%3}, {%4,%5,%6,%7}, {%8,%9}, {%0,%1,%2,%3};"
        : "+f"(d[0]), "+f"(d[1]), "+f"(d[2]), "+f"(d[3])
        : "r"(a[0]), "r"(a[1]), "r"(a[2]), "r"(a[3]), "r"(b[0]), "r"(b[1]));
}

// SMEM tile rows are 64B (32 bf16 = 4 16B chunks); chunk' = chunk ^ ((row>>1)&3)
__device__ __forceinline__ uint32_t swz(uint32_t row, uint32_t chunk) {
    return row * 64u + ((chunk ^ ((row >> 1) & 3u)) << 4);
}

// -------- bf16x3 HMMA GEMM: 128x128 tile, BK=32, 3 stages, 2 CTAs/SM -------
// MODE 0: C fp32 = alpha*acc.   MODE 1: (Ch,Cl) bf16 hi/lo split of acc.
#define OFF_AH 0
#define OFF_AL 8192
#define OFF_BH 16384
#define OFF_BL 24576
#define STAGE_BYTES 32768
#define GEMM_SMEM (3*STAGE_BYTES)       // 96 KB -> 2 CTAs/SM

template<int MODE>
__global__ __launch_bounds__(256, 2)
void gemm_bf16x3(const __nv_bfloat16* __restrict__ Ahi, const __nv_bfloat16* __restrict__ Alo,
                 const __nv_bfloat16* __restrict__ Bhi, const __nv_bfloat16* __restrict__ Blo,
                 float* __restrict__ C, __nv_bfloat16* __restrict__ Ch, __nv_bfloat16* __restrict__ Cl,
                 int M, int N, int K, long sA, long sB, long sC, float alpha)
{
    extern __shared__ char smem[];
    const uint32_t sbase = smem_u32(smem);
    const int tid = threadIdx.x;
    Ahi += (long)blockIdx.z * sA;  Alo += (long)blockIdx.z * sA;
    Bhi += (long)blockIdx.z * sB;  Blo += (long)blockIdx.z * sB;
    const int m0 = blockIdx.y * 128;
    const int n0 = blockIdx.x * 128;

    // ---- loader: row r = tid>>1, 2 chunks each of 4 parts -> 8 cp16 -------
    const int r  = tid >> 1;
    const int cb = (tid & 1) * 2;
    const __nv_bfloat16* pAh = Ahi + (long)(m0 + r) * K;
    const __nv_bfloat16* pAl = Alo + (long)(m0 + r) * K;
    const __nv_bfloat16* pBh = Bhi + (long)(n0 + r) * K;
    const __nv_bfloat16* pBl = Blo + (long)(n0 + r) * K;
    const uint32_t so0 = swz((uint32_t)r, (uint32_t)cb);
    const uint32_t so1 = swz((uint32_t)r, (uint32_t)cb + 1);

    auto load_chunk = [&](int j, int slot) {
        uint32_t st = sbase + (uint32_t)slot * STAGE_BYTES;
        long k0 = (long)j * 32 + (long)cb * 8;
        cp16(st + OFF_AH + so0, pAh + k0);  cp16(st + OFF_AH + so1, pAh + k0 + 8);
        cp16(st + OFF_AL + so0, pAl + k0);  cp16(st + OFF_AL + so1, pAl + k0 + 8);
        cp16(st + OFF_BH + so0, pBh + k0);  cp16(st + OFF_BH + so1, pBh + k0 + 8);
        cp16(st + OFF_BL + so0, pBl + k0);  cp16(st + OFF_BL + so1, pBl + k0 + 8);
    };

    // ---- compute setup: warp grid 4(m) x 2(n), warp tile 32x64 ------------
    const int lane = tid & 31;
    const int wid  = tid >> 5;
    const int wm   = wid & 3;
    const int wn   = wid >> 2;
    const int g    = lane >> 3;
    const int l7   = lane & 7;

    uint32_t aro[2], asz[2];
    #pragma unroll
    for (int mt = 0; mt < 2; mt++) {
        uint32_t rr = wm * 32 + mt * 16 + ((g & 1) << 3) + l7;
        aro[mt] = rr * 64u; asz[mt] = (rr >> 1) & 3u;
    }
    const uint32_t cbA = (uint32_t)(g >> 1);
    uint32_t bro[4], bsz[4];
    #pragma unroll
    for (int np = 0; np < 4; np++) {
        uint32_t rr = wn * 64 + np * 16 + ((g >> 1) << 3) + l7;
        bro[np] = rr * 64u; bsz[np] = (rr >> 1) & 3u;
    }
    const uint32_t cbB = (uint32_t)(g & 1);

    float acc[2][8][4];
    #pragma unroll
    for (int mt = 0; mt < 2; mt++)
        #pragma unroll
        for (int nt = 0; nt < 8; nt++)
            #pragma unroll
            for (int i = 0; i < 4; i++) acc[mt][nt][i] = 0.f;

    const int nch = K / 32;
    load_chunk(0, 0); CP_COMMIT();
    load_chunk(1, 1); CP_COMMIT();

    int slot = 0;
    for (int i = 0; i < nch; i++) {
        if (i + 2 < nch) { load_chunk(i + 2, (slot + 2) % 3); CP_COMMIT(); CP_WAIT(2); }
        else CP_WAIT(0);
        __syncthreads();

        uint32_t st = sbase + (uint32_t)slot * STAGE_BYTES;
        #pragma unroll
        for (int ks = 0; ks < 2; ks++) {
            uint32_t bh[4][4], bl[4][4];
            #pragma unroll
            for (int np = 0; np < 4; np++) {
                uint32_t off = bro[np] + ((((uint32_t)(ks << 1) + cbB) ^ bsz[np]) << 4);
                ldsm_x4(st + OFF_BH + off, bh[np]);
                ldsm_x4(st + OFF_BL + off, bl[np]);
            }
            #pragma unroll
            for (int mt = 0; mt < 2; mt++) {
                uint32_t ah[4], al[4];
                uint32_t off = aro[mt] + ((((uint32_t)(ks << 1) + cbA) ^ asz[mt]) << 4);
                ldsm_x4(st + OFF_AH + off, ah);
                ldsm_x4(st + OFF_AL + off, al);
                #pragma unroll
                for (int nt = 0; nt < 8; nt++)
                    mma16816(acc[mt][nt], ah, &bh[nt >> 1][(nt & 1) * 2]);
                #pragma unroll
                for (int nt = 0; nt < 8; nt++)
                    mma16816(acc[mt][nt], ah, &bl[nt >> 1][(nt & 1) * 2]);
                #pragma unroll
                for (int nt = 0; nt < 8; nt++)
                    mma16816(acc[mt][nt], al, &bh[nt >> 1][(nt & 1) * 2]);
            }
        }
        __syncthreads();
        slot = (slot + 1) % 3;
    }

    // ---- epilogue ----
    const long zC = (long)blockIdx.z * sC;
    #pragma unroll
    for (int mt = 0; mt < 2; mt++)
        #pragma unroll
        for (int nt = 0; nt < 8; nt++) {
            int r0 = m0 + wm * 32 + mt * 16 + (lane >> 2);
            int c0 = n0 + wn * 64 + nt * 8 + (lane & 3) * 2;
            float v0 = alpha * acc[mt][nt][0], v1 = alpha * acc[mt][nt][1];
            float v2 = alpha * acc[mt][nt][2], v3 = alpha * acc[mt][nt][3];
            if (MODE == 0) {
                *(float2*)&C[zC + (long)r0 * N + c0]       = make_float2(v0, v1);
                *(float2*)&C[zC + (long)(r0 + 8) * N + c0] = make_float2(v2, v3);
            } else {
                __nv_bfloat16 h0 = __float2bfloat16(v0), h1 = __float2bfloat16(v1);
                __nv_bfloat16 h2 = __float2bfloat16(v2), h3 = __float2bfloat16(v3);
                *(__nv_bfloat162*)&Ch[zC + (long)r0 * N + c0] = __nv_bfloat162(h0, h1);
                *(__nv_bfloat162*)&Ch[zC + (long)(r0 + 8) * N + c0] = __nv_bfloat162(h2, h3);
                __nv_bfloat16 q0 = __float2bfloat16(v0 - __bfloat162float(h0));
                __nv_bfloat16 q1 = __float2bfloat16(v1 - __bfloat162float(h1));
                __nv_bfloat16 q2 = __float2bfloat16(v2 - __bfloat162float(h2));
                __nv_bfloat16 q3 = __float2bfloat16(v3 - __bfloat162float(h3));
                *(__nv_bfloat162*)&Cl[zC + (long)r0 * N + c0] = __nv_bfloat162(q0, q1);
                *(__nv_bfloat162*)&Cl[zC + (long)(r0 + 8) * N + c0] = __nv_bfloat162(q2, q3);
            }
        }
}

// ---------------- split: x -> (bf16 hi, bf16 lo) ---------------------------
__global__ __launch_bounds__(256)
void split_kernel(const float* __restrict__ x, __nv_bfloat16* __restrict__ hi,
                  __nv_bfloat16* __restrict__ lo, long n)
{
    long i = ((long)blockIdx.x * 256 + threadIdx.x) * 4;
    if (i >= n) return;
    float4 v = *(const float4*)&x[i];
    __nv_bfloat16 h0 = __float2bfloat16(v.x), h1 = __float2bfloat16(v.y);
    __nv_bfloat16 h2 = __float2bfloat16(v.z), h3 = __float2bfloat16(v.w);
    __nv_bfloat16 l0 = __float2bfloat16(v.x - __bfloat162float(h0));
    __nv_bfloat16 l1 = __float2bfloat16(v.y - __bfloat162float(h1));
    __nv_bfloat16 l2 = __float2bfloat16(v.z - __bfloat162float(h2));
    __nv_bfloat16 l3 = __float2bfloat16(v.w - __bfloat162float(h3));
    ((__nv_bfloat162*)&hi[i])[0] = __nv_bfloat162(h0, h1);
    ((__nv_bfloat162*)&hi[i])[1] = __nv_bfloat162(h2, h3);
    ((__nv_bfloat162*)&lo[i])[0] = __nv_bfloat162(l0, l1);
    ((__nv_bfloat162*)&lo[i])[1] = __nv_bfloat162(l2, l3);
}

// ---------------- transpose + split: V[b][s][h] -> Vt[b][h][s] -------------
__global__ __launch_bounds__(256)
void transpose_split_kernel(const float* __restrict__ V, __nv_bfloat16* __restrict__ hi,
                            __nv_bfloat16* __restrict__ lo)
{
    __shared__ float t[32][33];
    int b = blockIdx.z;
    int s0 = blockIdx.x * 32, h0 = blockIdx.y * 32;
    const float* Vb = V + (long)b * SS * HH;
    #pragma unroll
    for (int r = 0; r < 4; r++)
        t[threadIdx.y + r * 8][threadIdx.x] =
            Vb[(long)(s0 + threadIdx.y + r * 8) * HH + h0 + threadIdx.x];
    __syncthreads();
    #pragma unroll
    for (int r = 0; r < 4; r++) {
        int h = h0 + threadIdx.y + r * 8;
        float v = t[threadIdx.x][threadIdx.y + r * 8];
        __nv_bfloat16 hh = __float2bfloat16(v);
        __nv_bfloat16 ll = __float2bfloat16(v - __bfloat162float(hh));
        long o = (long)b * HH * SS + (long)h * SS + s0 + threadIdx.x;
        hi[o] = hh; lo[o] = ll;
    }
}

// ---------------- fused RoPE + split ---------------------------------------
template<int WRITE_F32>
__global__ __launch_bounds__(256)
void rope_split_kernel(const float* __restrict__ x, const float* __restrict__ fcos,
                       const float* __restrict__ fsin, float* __restrict__ outf,
                       __nv_bfloat16* __restrict__ hi, __nv_bfloat16* __restrict__ lo)
{
    long idx = (long)blockIdx.x * blockDim.x + threadIdx.x;
    if (idx >= (long)NR * DD2) return;
    int row = (int)(idx >> 10);
    int j   = (int)(idx & (DD2 - 1));
    int s   = row & (SS - 1);
    float c  = fcos[(long)s * DD2 + j];
    float sn = fsin[(long)s * DD2 + j];
    float xr = x[(long)row * HH + j];
    float xi = x[(long)row * HH + j + DD2];
    float o0 = xr * c - xi * sn;
    float o1 = xr * sn + xi * c;
    if (WRITE_F32)
        ((float2*)outf)[(long)row * DD2 + j] = make_float2(o0, o1);
    __nv_bfloat16 h0 = __float2bfloat16(o0), h1 = __float2bfloat16(o1);
    ((__nv_bfloat162*)hi)[(long)row * DD2 + j] = __nv_bfloat162(h0, h1);
    __nv_bfloat16 l0 = __float2bfloat16(o0 - __bfloat162float(h0));
    __nv_bfloat16 l1 = __float2bfloat16(o1 - __bfloat162float(h1));
    ((__nv_bfloat162*)lo)[(long)row * DD2 + j] = __nv_bfloat162(l0, l1);
}

// ---------------- fused softmax + split ------------------------------------
__global__ __launch_bounds__(256)
void softmax_split_kernel(const float* __restrict__ sc,
                          __nv_bfloat16* __restrict__ ph, __nv_bfloat16* __restrict__ pl)
{
    const float* p = sc + (size_t)blockIdx.x * SS;
    __nv_bfloat16* oh = ph + (size_t)blockIdx.x * SS;
    __nv_bfloat16* ol = pl + (size_t)blockIdx.x * SS;
    const int tid = threadIdx.x;
    float4 v[4];
    float lmax = -3.0e38f;
    #pragma unroll
    for (int i = 0; i < 4; i++) {
        v[i] = ((const float4*)p)[tid + i * 256];
        lmax = fmaxf(lmax, fmaxf(fmaxf(v[i].x, v[i].y), fmaxf(v[i].z, v[i].w)));
    }
    __shared__ float redmax[8], redsum[8];
    #pragma unroll
    for (int o = 16; o > 0; o >>= 1) lmax = fmaxf(lmax, __shfl_xor_sync(~0u, lmax, o));
    if ((tid & 31) == 0) redmax[tid >> 5] = lmax;
    __syncthreads();
    float bmax = redmax[0];
    #pragma unroll
    for (int w = 1; w < 8; w++) bmax = fmaxf(bmax, redmax[w]);
    float lsum = 0.f;
    #pragma unroll
    for (int i = 0; i < 4; i++) {
        v[i].x = __expf(v[i].x - bmax); v[i].y = __expf(v[i].y - bmax);
        v[i].z = __expf(v[i].z - bmax); v[i].w = __expf(v[i].w - bmax);
        lsum += v[i].x + v[i].y + v[i].z + v[i].w;
    }
    #pragma unroll
    for (int o = 16; o > 0; o >>= 1) lsum += __shfl_xor_sync(~0u, lsum, o);
    if ((tid & 31) == 0) redsum[tid >> 5] = lsum;
    __syncthreads();
    float bsum = 0.f;
    #pragma unroll
    for (int w = 0; w < 8; w++) bsum += redsum[w];
    float rinv = 1.f / bsum;
    #pragma unroll
    for (int i = 0; i < 4; i++) {
        float a0 = v[i].x * rinv, a1 = v[i].y * rinv, a2 = v[i].z * rinv, a3 = v[i].w * rinv;
        int base = (tid + i * 256) * 4;
        __nv_bfloat16 h0 = __float2bfloat16(a0), h1 = __float2bfloat16(a1);
        __nv_bfloat16 h2 = __float2bfloat16(a2), h3 = __float2bfloat16(a3);
        ((__nv_bfloat162*)&oh[base])[0] = __nv_bfloat162(h0, h1);
        ((__nv_bfloat162*)&oh[base])[1] = __nv_bfloat162(h2, h3);
        __nv_bfloat16 l0 = __float2bfloat16(a0 - __bfloat162float(h0));
        __nv_bfloat16 l1 = __float2bfloat16(a1 - __bfloat162float(h1));
        __nv_bfloat16 l2 = __float2bfloat16(a2 - __bfloat162float(h2));
        __nv_bfloat16 l3 = __float2bfloat16(a3 - __bfloat162float(h3));
        ((__nv_bfloat162*)&ol[base])[0] = __nv_bfloat162(l0, l1);
        ((__nv_bfloat162*)&ol[base])[1] = __nv_bfloat162(l2, l3);
    }
}

// ---------------------------------------------------------------------------
extern "C" void kernel_launch(void* const* d_in, const int* in_sizes, int n_in,
                              void* d_out, int out_size)
{
    (void)in_sizes; (void)n_in; (void)out_size;
    const float* hs   = (const float*)d_in[0];
    const float* wq   = (const float*)d_in[1];
    const float* wk   = (const float*)d_in[2];
    const float* wv   = (const float*)d_in[3];
    const float* wo   = (const float*)d_in[4];
    const float* fcos = (const float*)d_in[5];
    const float* fsin = (const float*)d_in[6];

    float* out      = (float*)d_out;
    float* out_krot = out + NH;
    float* out_v    = out + 2 * NH;

    float *q, *k, *sc;
    __nv_bfloat16 *hsh, *hsl, *wh, *wl, *qrh, *qrl, *krh, *krl, *ph, *pl, *vth, *vtl, *cxh, *cxl;
    cudaGetSymbolAddress((void**)&q,   g_q);
    cudaGetSymbolAddress((void**)&k,   g_k);
    cudaGetSymbolAddress((void**)&sc,  g_scores);
    cudaGetSymbolAddress((void**)&hsh, g_hs_h);  cudaGetSymbolAddress((void**)&hsl, g_hs_l);
    cudaGetSymbolAddress((void**)&wh,  g_w_h);   cudaGetSymbolAddress((void**)&wl,  g_w_l);
    cudaGetSymbolAddress((void**)&qrh, g_qr_h);  cudaGetSymbolAddress((void**)&qrl, g_qr_l);
    cudaGetSymbolAddress((void**)&krh, g_kr_h);  cudaGetSymbolAddress((void**)&krl, g_kr_l);
    cudaGetSymbolAddress((void**)&ph,  g_p_h);   cudaGetSymbolAddress((void**)&pl,  g_p_l);
    cudaGetSymbolAddress((void**)&vth, g_vt_h);  cudaGetSymbolAddress((void**)&vtl, g_vt_l);
    cudaGetSymbolAddress((void**)&cxh, g_cx_h);  cudaGetSymbolAddress((void**)&cxl, g_cx_l);

    cudaFuncSetAttribute(gemm_bf16x3<0>, cudaFuncAttributeMaxDynamicSharedMemorySize, GEMM_SMEM);
    cudaFuncSetAttribute(gemm_bf16x3<1>, cudaFuncAttributeMaxDynamicSharedMemorySize, GEMM_SMEM);

    const long WN = (long)HH * HH;
    auto SPLIT = [&](const float* x, __nv_bfloat16* h, __nv_bfloat16* l, long n) {
        split_kernel<<<(unsigned)((n / 4 + 255) / 256), 256>>>(x, h, l, n);
    };

    // 0) split inputs
    SPLIT(hs, hsh, hsl, NH);
    SPLIT(wq, wh + 0 * WN, wl + 0 * WN, WN);
    SPLIT(wk, wh + 1 * WN, wl + 1 * WN, WN);
    SPLIT(wv, wh + 2 * WN, wl + 2 * WN, WN);
    SPLIT(wo, wh + 3 * WN, wl + 3 * WN, WN);

    // 1) projections: [8192,2048] @ [2048,2048]^T
    dim3 gP(HH / 128, NR / 128, 1);
    gemm_bf16x3<0><<<gP, 256, GEMM_SMEM>>>(hsh, hsl, wh + 0 * WN, wl + 0 * WN, q,     nullptr, nullptr, NR, HH, HH, 0, 0, 0, 1.f);
    gemm_bf16x3<0><<<gP, 256, GEMM_SMEM>>>(hsh, hsl, wh + 1 * WN, wl + 1 * WN, k,     nullptr, nullptr, NR, HH, HH, 0, 0, 0, 1.f);
    gemm_bf16x3<0><<<gP, 256, GEMM_SMEM>>>(hsh, hsl, wh + 2 * WN, wl + 2 * WN, out_v, nullptr, nullptr, NR, HH, HH, 0, 0, 0, 1.f);

    // 2) fused RoPE + split
    int ropeBlocks = (int)(((long)NR * DD2 + 255) / 256);
    rope_split_kernel<0><<<ropeBlocks, 256>>>(q, fcos, fsin, nullptr,   qrh, qrl);
    rope_split_kernel<1><<<ropeBlocks, 256>>>(k, fcos, fsin, out_krot, krh, krl);

    // 3) scores = 0.125 * Qr Kr^T  (batched)
    dim3 gS(SS / 128, SS / 128, BB);
    gemm_bf16x3<0><<<gS, 256, GEMM_SMEM>>>(qrh, qrl, krh, krl, sc, nullptr, nullptr, SS, SS, HH,
                                           (long)SS * HH, (long)SS * HH, (long)SS * SS, ATT_SCALE);

    // 4) fused softmax + split -> P hi/lo
    softmax_split_kernel<<<NR, 256>>>(sc, ph, pl);

    // 5) V transpose + split
    dim3 gT(SS / 32, HH / 32, BB);
    transpose_split_kernel<<<gT, dim3(32, 8)>>>(out_v, vth, vtl);

    // 6) ctx = P @ V^T -> split epilogue directly to cx hi/lo
    dim3 gC(HH / 128, SS / 128, BB);
    gemm_bf16x3<1><<<gC, 256, GEMM_SMEM>>>(ph, pl, vth, vtl, nullptr, cxh, cxl, SS, HH, SS,
                                           (long)SS * SS, (long)HH * SS, (long)SS * HH, 1.f);

    // 7) output projection
    gemm_bf16x3<0><<<gP, 256, GEMM_SMEM>>>(cxh, cxl, wh + 3 * WN, wl + 3 * WN, out, nullptr, nullptr, NR, HH, HH, 0, 0, 0, 1.f);
}

// round 8
// speedup vs baseline: 5.1914x; 1.0970x over previous
#include <cuda_runtime.h>
#include <cuda_bf16.h>
#include <cstdint>

#define BB 2
#define SS 4096
#define HH 2048
#define DD2 1024
#define NR (BB*SS)            // 8192
#define NH ((long)NR*HH)      // 16,777,216
#define NSCORE ((long)BB*SS*SS)
#define ATT_SCALE 0.125f

// ---------------- scratch (__device__ globals; no allocs allowed) ----------
__device__ float g_q[NH];
__device__ float g_k[NH];
__device__ float g_scores[NSCORE];

__device__ __nv_bfloat16 g_hs_h[NH],  g_hs_l[NH];
__device__ __nv_bfloat16 g_w_h[4L*HH*HH], g_w_l[4L*HH*HH];
__device__ __nv_bfloat16 g_qr_h[NH], g_qr_l[NH];
__device__ __nv_bfloat16 g_kr_h[NH], g_kr_l[NH];
__device__ __nv_bfloat16 g_p_h[NSCORE], g_p_l[NSCORE];
__device__ __nv_bfloat16 g_vt_h[NH], g_vt_l[NH];
__device__ __nv_bfloat16 g_cx_h[NH], g_cx_l[NH];

// ---------------- PTX helpers (base sm_103 ISA only) -----------------------
__device__ __forceinline__ uint32_t smem_u32(const void* p) {
    uint32_t a;
    asm("{ .reg .u64 t; cvta.to.shared.u64 t, %1; cvt.u32.u64 %0, t; }" : "=r"(a) : "l"(p));
    return a;
}
#define CP_COMMIT()  asm volatile("cp.async.commit_group;" ::: "memory")
#define CP_WAIT(n)   asm volatile("cp.async.wait_group %0;" :: "n"(n) : "memory")

__device__ __forceinline__ void cp16(uint32_t dst, const void* src) {
    asm volatile("cp.async.cg.shared.global [%0], [%1], 16;"
                 :: "r"(dst), "l"(__cvta_generic_to_global(src)) : "memory");
}
__device__ __forceinline__ void ldsm_x4(uint32_t addr, uint32_t* r) {
    asm volatile("ldmatrix.sync.aligned.m8n8.x4.shared.b16 {%0,%1,%2,%3}, [%4];"
        : "=r"(r[0]), "=r"(r[1]), "=r"(r[2]), "=r"(r[3]) : "r"(addr));
}
__device__ __forceinline__ void mma16816(float* d, const uint32_t* a, const uint32_t* b) {
    asm volatile("mma.sync.aligned.m16n8k16.row.col.f32.bf16.bf16.f32 "
        "{%0,%1,%2,%3}, {%4,%5,%6,%7}, {%8,%9}, {%0,%1,%2,%3};"
        : "+f"(d[0]), "+f"(d[1]), "+f"(d[2]), "+f"(d[3])
        : "r"(a[0]), "r"(a[1]), "r"(a[2]), "r"(a[3]), "r"(b[0]), "r"(b[1]));
}

// SMEM tile rows are 64B (32 bf16 = 4 16B chunks); chunk' = chunk ^ ((row>>1)&3)
__device__ __forceinline__ uint32_t swz(uint32_t row, uint32_t chunk) {
    return row * 64u + ((chunk ^ ((row >> 1) & 3u)) << 4);
}

// -------- bf16x3 HMMA GEMM: 128x128 tile, BK=32, 3 stages, 2 CTAs/SM -------
// MODE 0: C fp32.  MODE 1: (Ch,Cl) bf16 hi/lo split.  MODE 2: fp32 to C/C1/C2 by z.
#define OFF_AH 0
#define OFF_AL 8192
#define OFF_BH 16384
#define OFF_BL 24576
#define STAGE_BYTES 32768
#define GEMM_SMEM (3*STAGE_BYTES)       // 96 KB -> 2 CTAs/SM

template<int MODE>
__global__ __launch_bounds__(256, 2)
void gemm_bf16x3(const __nv_bfloat16* __restrict__ Ahi, const __nv_bfloat16* __restrict__ Alo,
                 const __nv_bfloat16* __restrict__ Bhi, const __nv_bfloat16* __restrict__ Blo,
                 float* __restrict__ C, float* __restrict__ C1, float* __restrict__ C2,
                 __nv_bfloat16* __restrict__ Ch, __nv_bfloat16* __restrict__ Cl,
                 int M, int N, int K, long sA, long sB, long sC, float alpha)
{
    extern __shared__ char smem[];
    const uint32_t sbase = smem_u32(smem);
    const int tid = threadIdx.x;
    const int z = blockIdx.z;
    Ahi += (long)z * sA;  Alo += (long)z * sA;
    Bhi += (long)z * sB;  Blo += (long)z * sB;
    float* dst = C;
    if (MODE == 2) dst = (z == 0) ? C : ((z == 1) ? C1 : C2);
    const int m0 = blockIdx.y * 128;
    const int n0 = blockIdx.x * 128;

    // ---- loader: row r = tid>>1, 2 chunks each of 4 parts -> 8 cp16 -------
    const int r  = tid >> 1;
    const int cb = (tid & 1) * 2;
    const __nv_bfloat16* pAh = Ahi + (long)(m0 + r) * K;
    const __nv_bfloat16* pAl = Alo + (long)(m0 + r) * K;
    const __nv_bfloat16* pBh = Bhi + (long)(n0 + r) * K;
    const __nv_bfloat16* pBl = Blo + (long)(n0 + r) * K;
    const uint32_t so0 = swz((uint32_t)r, (uint32_t)cb);
    const uint32_t so1 = swz((uint32_t)r, (uint32_t)cb + 1);

    auto load_chunk = [&](int j, int slot) {
        uint32_t st = sbase + (uint32_t)slot * STAGE_BYTES;
        long k0 = (long)j * 32 + (long)cb * 8;
        cp16(st + OFF_AH + so0, pAh + k0);  cp16(st + OFF_AH + so1, pAh + k0 + 8);
        cp16(st + OFF_AL + so0, pAl + k0);  cp16(st + OFF_AL + so1, pAl + k0 + 8);
        cp16(st + OFF_BH + so0, pBh + k0);  cp16(st + OFF_BH + so1, pBh + k0 + 8);
        cp16(st + OFF_BL + so0, pBl + k0);  cp16(st + OFF_BL + so1, pBl + k0 + 8);
    };

    // ---- compute setup: warp grid 4(m) x 2(n), warp tile 32x64 ------------
    const int lane = tid & 31;
    const int wid  = tid >> 5;
    const int wm   = wid & 3;
    const int wn   = wid >> 2;
    const int g    = lane >> 3;
    const int l7   = lane & 7;

    uint32_t aro[2], asz[2];
    #pragma unroll
    for (int mt = 0; mt < 2; mt++) {
        uint32_t rr = wm * 32 + mt * 16 + ((g & 1) << 3) + l7;
        aro[mt] = rr * 64u; asz[mt] = (rr >> 1) & 3u;
    }
    const uint32_t cbA = (uint32_t)(g >> 1);
    uint32_t bro[4], bsz[4];
    #pragma unroll
    for (int np = 0; np < 4; np++) {
        uint32_t rr = wn * 64 + np * 16 + ((g >> 1) << 3) + l7;
        bro[np] = rr * 64u; bsz[np] = (rr >> 1) & 3u;
    }
    const uint32_t cbB = (uint32_t)(g & 1);

    float acc[2][8][4];
    #pragma unroll
    for (int mt = 0; mt < 2; mt++)
        #pragma unroll
        for (int nt = 0; nt < 8; nt++)
            #pragma unroll
            for (int i = 0; i < 4; i++) acc[mt][nt][i] = 0.f;

    const int nch = K / 32;
    load_chunk(0, 0); CP_COMMIT();
    load_chunk(1, 1); CP_COMMIT();

    int slot = 0;
    for (int i = 0; i < nch; i++) {
        if (i == nch - 1) CP_WAIT(0);
        else              CP_WAIT(1);
        __syncthreads();           // chunk i visible; all warps done with slot (i-1)%3
        if (i + 2 < nch) {
            int ns = slot + 2; if (ns >= 3) ns -= 3;
            load_chunk(i + 2, ns); CP_COMMIT();
        }

        uint32_t st = sbase + (uint32_t)slot * STAGE_BYTES;
        #pragma unroll
        for (int ks = 0; ks < 2; ks++) {
            uint32_t bh[4][4], bl[4][4];
            #pragma unroll
            for (int np = 0; np < 4; np++) {
                uint32_t off = bro[np] + ((((uint32_t)(ks << 1) + cbB) ^ bsz[np]) << 4);
                ldsm_x4(st + OFF_BH + off, bh[np]);
                ldsm_x4(st + OFF_BL + off, bl[np]);
            }
            #pragma unroll
            for (int mt = 0; mt < 2; mt++) {
                uint32_t ah[4], al[4];
                uint32_t off = aro[mt] + ((((uint32_t)(ks << 1) + cbA) ^ asz[mt]) << 4);
                ldsm_x4(st + OFF_AH + off, ah);
                ldsm_x4(st + OFF_AL + off, al);
                #pragma unroll
                for (int nt = 0; nt < 8; nt++)
                    mma16816(acc[mt][nt], ah, &bh[nt >> 1][(nt & 1) * 2]);
                #pragma unroll
                for (int nt = 0; nt < 8; nt++)
                    mma16816(acc[mt][nt], ah, &bl[nt >> 1][(nt & 1) * 2]);
                #pragma unroll
                for (int nt = 0; nt < 8; nt++)
                    mma16816(acc[mt][nt], al, &bh[nt >> 1][(nt & 1) * 2]);
            }
        }
        slot++; if (slot >= 3) slot -= 3;
    }

    // ---- epilogue ----
    const long zC = (MODE == 2) ? 0 : (long)z * sC;
    #pragma unroll
    for (int mt = 0; mt < 2; mt++)
        #pragma unroll
        for (int nt = 0; nt < 8; nt++) {
            int r0 = m0 + wm * 32 + mt * 16 + (lane >> 2);
            int c0 = n0 + wn * 64 + nt * 8 + (lane & 3) * 2;
            float v0 = alpha * acc[mt][nt][0], v1 = alpha * acc[mt][nt][1];
            float v2 = alpha * acc[mt][nt][2], v3 = alpha * acc[mt][nt][3];
            if (MODE != 1) {
                *(float2*)&dst[zC + (long)r0 * N + c0]       = make_float2(v0, v1);
                *(float2*)&dst[zC + (long)(r0 + 8) * N + c0] = make_float2(v2, v3);
            } else {
                __nv_bfloat16 h0 = __float2bfloat16(v0), h1 = __float2bfloat16(v1);
                __nv_bfloat16 h2 = __float2bfloat16(v2), h3 = __float2bfloat16(v3);
                *(__nv_bfloat162*)&Ch[zC + (long)r0 * N + c0] = __nv_bfloat162(h0, h1);
                *(__nv_bfloat162*)&Ch[zC + (long)(r0 + 8) * N + c0] = __nv_bfloat162(h2, h3);
                __nv_bfloat16 q0 = __float2bfloat16(v0 - __bfloat162float(h0));
                __nv_bfloat16 q1 = __float2bfloat16(v1 - __bfloat162float(h1));
                __nv_bfloat16 q2 = __float2bfloat16(v2 - __bfloat162float(h2));
                __nv_bfloat16 q3 = __float2bfloat16(v3 - __bfloat162float(h3));
                *(__nv_bfloat162*)&Cl[zC + (long)r0 * N + c0] = __nv_bfloat162(q0, q1);
                *(__nv_bfloat162*)&Cl[zC + (long)(r0 + 8) * N + c0] = __nv_bfloat162(q2, q3);
            }
        }
}

// ---------------- split: x -> (bf16 hi, bf16 lo) ---------------------------
__global__ __launch_bounds__(256)
void split_kernel(const float* __restrict__ x, __nv_bfloat16* __restrict__ hi,
                  __nv_bfloat16* __restrict__ lo, long n)
{
    long i = ((long)blockIdx.x * 256 + threadIdx.x) * 4;
    if (i >= n) return;
    float4 v = *(const float4*)&x[i];
    __nv_bfloat16 h0 = __float2bfloat16(v.x), h1 = __float2bfloat16(v.y);
    __nv_bfloat16 h2 = __float2bfloat16(v.z), h3 = __float2bfloat16(v.w);
    __nv_bfloat16 l0 = __float2bfloat16(v.x - __bfloat162float(h0));
    __nv_bfloat16 l1 = __float2bfloat16(v.y - __bfloat162float(h1));
    __nv_bfloat16 l2 = __float2bfloat16(v.z - __bfloat162float(h2));
    __nv_bfloat16 l3 = __float2bfloat16(v.w - __bfloat162float(h3));
    ((__nv_bfloat162*)&hi[i])[0] = __nv_bfloat162(h0, h1);
    ((__nv_bfloat162*)&hi[i])[1] = __nv_bfloat162(h2, h3);
    ((__nv_bfloat162*)&lo[i])[0] = __nv_bfloat162(l0, l1);
    ((__nv_bfloat162*)&lo[i])[1] = __nv_bfloat162(l2, l3);
}

// ---------------- transpose + split: V[b][s][h] -> Vt[b][h][s] -------------
__global__ __launch_bounds__(256)
void transpose_split_kernel(const float* __restrict__ V, __nv_bfloat16* __restrict__ hi,
                            __nv_bfloat16* __restrict__ lo)
{
    __shared__ float t[32][33];
    int b = blockIdx.z;
    int s0 = blockIdx.x * 32, h0 = blockIdx.y * 32;
    const float* Vb = V + (long)b * SS * HH;
    #pragma unroll
    for (int r = 0; r < 4; r++)
        t[threadIdx.y + r * 8][threadIdx.x] =
            Vb[(long)(s0 + threadIdx.y + r * 8) * HH + h0 + threadIdx.x];
    __syncthreads();
    #pragma unroll
    for (int r = 0; r < 4; r++) {
        int h = h0 + threadIdx.y + r * 8;
        float v = t[threadIdx.x][threadIdx.y + r * 8];
        __nv_bfloat16 hh = __float2bfloat16(v);
        __nv_bfloat16 ll = __float2bfloat16(v - __bfloat162float(hh));
        long o = (long)b * HH * SS + (long)h * SS + s0 + threadIdx.x;
        hi[o] = hh; lo[o] = ll;
    }
}

// ---------------- fused RoPE + split (q and k in one launch) ---------------
__global__ __launch_bounds__(256)
void rope_split2_kernel(const float* __restrict__ xq, const float* __restrict__ xk,
                        const float* __restrict__ fcos, const float* __restrict__ fsin,
                        float* __restrict__ krotf,
                        __nv_bfloat16* __restrict__ qh, __nv_bfloat16* __restrict__ ql,
                        __nv_bfloat16* __restrict__ kh, __nv_bfloat16* __restrict__ kl)
{
    long idx = (long)blockIdx.x * blockDim.x + threadIdx.x;
    if (idx >= (long)NR * DD2) return;
    int row = (int)(idx >> 10);
    int j   = (int)(idx & (DD2 - 1));
    int s   = row & (SS - 1);
    float c  = fcos[(long)s * DD2 + j];
    float sn = fsin[(long)s * DD2 + j];
    const float* x = (blockIdx.y == 0) ? xq : xk;
    __nv_bfloat16* hi = (blockIdx.y == 0) ? qh : kh;
    __nv_bfloat16* lo = (blockIdx.y == 0) ? ql : kl;
    float xr = x[(long)row * HH + j];
    float xi = x[(long)row * HH + j + DD2];
    float o0 = xr * c - xi * sn;
    float o1 = xr * sn + xi * c;
    if (blockIdx.y == 1)
        ((float2*)krotf)[(long)row * DD2 + j] = make_float2(o0, o1);
    __nv_bfloat16 h0 = __float2bfloat16(o0), h1 = __float2bfloat16(o1);
    ((__nv_bfloat162*)hi)[(long)row * DD2 + j] = __nv_bfloat162(h0, h1);
    __nv_bfloat16 l0 = __float2bfloat16(o0 - __bfloat162float(h0));
    __nv_bfloat16 l1 = __float2bfloat16(o1 - __bfloat162float(h1));
    ((__nv_bfloat162*)lo)[(long)row * DD2 + j] = __nv_bfloat162(l0, l1);
}

// ---------------- fused softmax + split ------------------------------------
__global__ __launch_bounds__(256)
void softmax_split_kernel(const float* __restrict__ sc,
                          __nv_bfloat16* __restrict__ ph, __nv_bfloat16* __restrict__ pl)
{
    const float* p = sc + (size_t)blockIdx.x * SS;
    __nv_bfloat16* oh = ph + (size_t)blockIdx.x * SS;
    __nv_bfloat16* ol = pl + (size_t)blockIdx.x * SS;
    const int tid = threadIdx.x;
    float4 v[4];
    float lmax = -3.0e38f;
    #pragma unroll
    for (int i = 0; i < 4; i++) {
        v[i] = ((const float4*)p)[tid + i * 256];
        lmax = fmaxf(lmax, fmaxf(fmaxf(v[i].x, v[i].y), fmaxf(v[i].z, v[i].w)));
    }
    __shared__ float redmax[8], redsum[8];
    #pragma unroll
    for (int o = 16; o > 0; o >>= 1) lmax = fmaxf(lmax, __shfl_xor_sync(~0u, lmax, o));
    if ((tid & 31) == 0) redmax[tid >> 5] = lmax;
    __syncthreads();
    float bmax = redmax[0];
    #pragma unroll
    for (int w = 1; w < 8; w++) bmax = fmaxf(bmax, redmax[w]);
    float lsum = 0.f;
    #pragma unroll
    for (int i = 0; i < 4; i++) {
        v[i].x = __expf(v[i].x - bmax); v[i].y = __expf(v[i].y - bmax);
        v[i].z = __expf(v[i].z - bmax); v[i].w = __expf(v[i].w - bmax);
        lsum += v[i].x + v[i].y + v[i].z + v[i].w;
    }
    #pragma unroll
    for (int o = 16; o > 0; o >>= 1) lsum += __shfl_xor_sync(~0u, lsum, o);
    if ((tid & 31) == 0) redsum[tid >> 5] = lsum;
    __syncthreads();
    float bsum = 0.f;
    #pragma unroll
    for (int w = 0; w < 8; w++) bsum += redsum[w];
    float rinv = 1.f / bsum;
    #pragma unroll
    for (int i = 0; i < 4; i++) {
        float a0 = v[i].x * rinv, a1 = v[i].y * rinv, a2 = v[i].z * rinv, a3 = v[i].w * rinv;
        int base = (tid + i * 256) * 4;
        __nv_bfloat16 h0 = __float2bfloat16(a0), h1 = __float2bfloat16(a1);
        __nv_bfloat16 h2 = __float2bfloat16(a2), h3 = __float2bfloat16(a3);
        ((__nv_bfloat162*)&oh[base])[0] = __nv_bfloat162(h0, h1);
        ((__nv_bfloat162*)&oh[base])[1] = __nv_bfloat162(h2, h3);
        __nv_bfloat16 l0 = __float2bfloat16(a0 - __bfloat162float(h0));
        __nv_bfloat16 l1 = __float2bfloat16(a1 - __bfloat162float(h1));
        __nv_bfloat16 l2 = __float2bfloat16(a2 - __bfloat162float(h2));
        __nv_bfloat16 l3 = __float2bfloat16(a3 - __bfloat162float(h3));
        ((__nv_bfloat162*)&ol[base])[0] = __nv_bfloat162(l0, l1);
        ((__nv_bfloat162*)&ol[base])[1] = __nv_bfloat162(l2, l3);
    }
}

// ---------------------------------------------------------------------------
extern "C" void kernel_launch(void* const* d_in, const int* in_sizes, int n_in,
                              void* d_out, int out_size)
{
    (void)in_sizes; (void)n_in; (void)out_size;
    const float* hs   = (const float*)d_in[0];
    const float* wq   = (const float*)d_in[1];
    const float* wk   = (const float*)d_in[2];
    const float* wv   = (const float*)d_in[3];
    const float* wo   = (const float*)d_in[4];
    const float* fcos = (const float*)d_in[5];
    const float* fsin = (const float*)d_in[6];

    float* out      = (float*)d_out;
    float* out_krot = out + NH;
    float* out_v    = out + 2 * NH;

    float *q, *k, *sc;
    __nv_bfloat16 *hsh, *hsl, *wh, *wl, *qrh, *qrl, *krh, *krl, *ph, *pl, *vth, *vtl, *cxh, *cxl;
    cudaGetSymbolAddress((void**)&q,   g_q);
    cudaGetSymbolAddress((void**)&k,   g_k);
    cudaGetSymbolAddress((void**)&sc,  g_scores);
    cudaGetSymbolAddress((void**)&hsh, g_hs_h);  cudaGetSymbolAddress((void**)&hsl, g_hs_l);
    cudaGetSymbolAddress((void**)&wh,  g_w_h);   cudaGetSymbolAddress((void**)&wl,  g_w_l);
    cudaGetSymbolAddress((void**)&qrh, g_qr_h);  cudaGetSymbolAddress((void**)&qrl, g_qr_l);
    cudaGetSymbolAddress((void**)&krh, g_kr_h);  cudaGetSymbolAddress((void**)&krl, g_kr_l);
    cudaGetSymbolAddress((void**)&ph,  g_p_h);   cudaGetSymbolAddress((void**)&pl,  g_p_l);
    cudaGetSymbolAddress((void**)&vth, g_vt_h);  cudaGetSymbolAddress((void**)&vtl, g_vt_l);
    cudaGetSymbolAddress((void**)&cxh, g_cx_h);  cudaGetSymbolAddress((void**)&cxl, g_cx_l);

    cudaFuncSetAttribute(gemm_bf16x3<0>, cudaFuncAttributeMaxDynamicSharedMemorySize, GEMM_SMEM);
    cudaFuncSetAttribute(gemm_bf16x3<1>, cudaFuncAttributeMaxDynamicSharedMemorySize, GEMM_SMEM);
    cudaFuncSetAttribute(gemm_bf16x3<2>, cudaFuncAttributeMaxDynamicSharedMemorySize, GEMM_SMEM);

    const long WN = (long)HH * HH;
    auto SPLIT = [&](const float* x, __nv_bfloat16* h, __nv_bfloat16* l, long n) {
        split_kernel<<<(unsigned)((n / 4 + 255) / 256), 256>>>(x, h, l, n);
    };

    // 0) split inputs
    SPLIT(hs, hsh, hsl, NH);
    SPLIT(wq, wh + 0 * WN, wl + 0 * WN, WN);
    SPLIT(wk, wh + 1 * WN, wl + 1 * WN, WN);
    SPLIT(wv, wh + 2 * WN, wl + 2 * WN, WN);
    SPLIT(wo, wh + 3 * WN, wl + 3 * WN, WN);

    // 1) QKV merged: z selects weight block and destination
    dim3 gQKV(HH / 128, NR / 128, 3);
    gemm_bf16x3<2><<<gQKV, 256, GEMM_SMEM>>>(hsh, hsl, wh, wl, q, k, out_v,
                                             nullptr, nullptr, NR, HH, HH, 0, WN, 0, 1.f);

    // 2) fused RoPE + split, q and k in one launch
    dim3 gR((unsigned)(((long)NR * DD2 + 255) / 256), 2);
    rope_split2_kernel<<<gR, 256>>>(q, k, fcos, fsin, out_krot, qrh, qrl, krh, krl);

    // 3) scores = 0.125 * Qr Kr^T  (batched)
    dim3 gS(SS / 128, SS / 128, BB);
    gemm_bf16x3<0><<<gS, 256, GEMM_SMEM>>>(qrh, qrl, krh, krl, sc, nullptr, nullptr,
                                           nullptr, nullptr, SS, SS, HH,
                                           (long)SS * HH, (long)SS * HH, (long)SS * SS, ATT_SCALE);

    // 4) fused softmax + split -> P hi/lo
    softmax_split_kernel<<<NR, 256>>>(sc, ph, pl);

    // 5) V transpose + split
    dim3 gT(SS / 32, HH / 32, BB);
    transpose_split_kernel<<<gT, dim3(32, 8)>>>(out_v, vth, vtl);

    // 6) ctx = P @ V^T -> split epilogue directly to cx hi/lo
    dim3 gC(HH / 128, SS / 128, BB);
    gemm_bf16x3<1><<<gC, 256, GEMM_SMEM>>>(ph, pl, vth, vtl, nullptr, nullptr, nullptr,
                                           cxh, cxl, SS, HH, SS,
                                           (long)SS * SS, (long)HH * SS, (long)SS * HH, 1.f);

    // 7) output projection
    dim3 gO(HH / 128, NR / 128, 1);
    gemm_bf16x3<0><<<gO, 256, GEMM_SMEM>>>(cxh, cxl, wh + 3 * WN, wl + 3 * WN, out,
                                           nullptr, nullptr, nullptr, nullptr,
                                           NR, HH, HH, 0, 0, 0, 1.f);
}

// round 9
// speedup vs baseline: 5.2676x; 1.0147x over previous
#include <cuda_runtime.h>
#include <cuda_bf16.h>
#include <cstdint>

#define BB 2
#define SS 4096
#define HH 2048
#define DD2 1024
#define NR (BB*SS)            // 8192
#define NH ((long)NR*HH)      // 16,777,216
#define NSCORE ((long)BB*SS*SS)
#define ATT_SCALE 0.125f
#define WN ((long)HH*HH)

// ---------------- scratch (__device__ globals; no allocs allowed) ----------
__device__ float g_scores[NSCORE];

__device__ __nv_bfloat16 g_hs_h[NH],  g_hs_l[NH];
__device__ __nv_bfloat16 g_w_h[4L*HH*HH], g_w_l[4L*HH*HH];
__device__ __nv_bfloat16 g_qkr_h[2*NH], g_qkr_l[2*NH];   // q_rot | k_rot hi/lo
__device__ __nv_bfloat16 g_p_h[NSCORE], g_p_l[NSCORE];
__device__ __nv_bfloat16 g_vt_h[NH], g_vt_l[NH];
__device__ __nv_bfloat16 g_cx_h[NH], g_cx_l[NH];

// ---------------- PTX helpers (base sm_103 ISA only) -----------------------
__device__ __forceinline__ uint32_t smem_u32(const void* p) {
    uint32_t a;
    asm("{ .reg .u64 t; cvta.to.shared.u64 t, %1; cvt.u32.u64 %0, t; }" : "=r"(a) : "l"(p));
    return a;
}
#define CP_COMMIT()  asm volatile("cp.async.commit_group;" ::: "memory")
#define CP_WAIT(n)   asm volatile("cp.async.wait_group %0;" :: "n"(n) : "memory")

__device__ __forceinline__ void cp16(uint32_t dst, const void* src) {
    asm volatile("cp.async.cg.shared.global [%0], [%1], 16;"
                 :: "r"(dst), "l"(__cvta_generic_to_global(src)) : "memory");
}
__device__ __forceinline__ void ldsm_x4(uint32_t addr, uint32_t* r) {
    asm volatile("ldmatrix.sync.aligned.m8n8.x4.shared.b16 {%0,%1,%2,%3}, [%4];"
        : "=r"(r[0]), "=r"(r[1]), "=r"(r[2]), "=r"(r[3]) : "r"(addr));
}
__device__ __forceinline__ void mma16816(float* d, const uint32_t* a, const uint32_t* b) {
    asm volatile("mma.sync.aligned.m16n8k16.row.col.f32.bf16.bf16.f32 "
        "{%0,%1,%2,%3}, {%4,%5,%6,%7}, {%8,%9}, {%0,%1,%2,%3};"
        : "+f"(d[0]), "+f"(d[1]), "+f"(d[2]), "+f"(d[3])
        : "r"(a[0]), "r"(a[1]), "r"(a[2]), "r"(a[3]), "r"(b[0]), "r"(b[1]));
}

// SMEM tile rows are 64B (32 bf16 = 4 16B chunks); chunk' = chunk ^ ((row>>1)&3)
__device__ __forceinline__ uint32_t swz(uint32_t row, uint32_t chunk) {
    return row * 64u + ((chunk ^ ((row >> 1) & 3u)) << 4);
}

// -------- bf16x3 HMMA GEMM: 128x128 tile, BK=32, 3 stages, 2 CTAs/SM -------
// MODE 0: C fp32.
// MODE 1: (Ch,Cl) bf16 hi/lo split of acc.
// MODE 3: merged QKV+RoPE. z=0: rope->Ch/Cl[0]; z=1: rope->C1 fp32 + Ch/Cl[NH]; z=2: C fp32 (v).
//         Requires wq/wk stored with permuted rows [0,1024,1,1025,...].
#define OFF_AH 0
#define OFF_AL 8192
#define OFF_BH 16384
#define OFF_BL 24576
#define STAGE_BYTES 32768
#define GEMM_SMEM (3*STAGE_BYTES)       // 96 KB -> 2 CTAs/SM

template<int MODE>
__global__ __launch_bounds__(256, 2)
void gemm_bf16x3(const __nv_bfloat16* __restrict__ Ahi, const __nv_bfloat16* __restrict__ Alo,
                 const __nv_bfloat16* __restrict__ Bhi, const __nv_bfloat16* __restrict__ Blo,
                 float* __restrict__ C, float* __restrict__ C1,
                 __nv_bfloat16* __restrict__ Ch, __nv_bfloat16* __restrict__ Cl,
                 const float* __restrict__ Fc, const float* __restrict__ Fs,
                 int M, int N, int K, long sA, long sB, long sC, float alpha)
{
    extern __shared__ char smem[];
    const uint32_t sbase = smem_u32(smem);
    const int tid = threadIdx.x;
    const int z = blockIdx.z;
    Ahi += (long)z * sA;  Alo += (long)z * sA;
    Bhi += (long)z * sB;  Blo += (long)z * sB;
    const int m0 = blockIdx.y * 128;
    const int n0 = blockIdx.x * 128;

    // ---- loader: row r = tid>>1, 2 chunks each of 4 parts -> 8 cp16 -------
    const int r  = tid >> 1;
    const int cb = (tid & 1) * 2;
    const __nv_bfloat16* pAh = Ahi + (long)(m0 + r) * K;
    const __nv_bfloat16* pAl = Alo + (long)(m0 + r) * K;
    const __nv_bfloat16* pBh = Bhi + (long)(n0 + r) * K;
    const __nv_bfloat16* pBl = Blo + (long)(n0 + r) * K;
    const uint32_t so0 = swz((uint32_t)r, (uint32_t)cb);
    const uint32_t so1 = swz((uint32_t)r, (uint32_t)cb + 1);

    auto load_chunk = [&](int j, int slot) {
        uint32_t st = sbase + (uint32_t)slot * STAGE_BYTES;
        long k0 = (long)j * 32 + (long)cb * 8;
        cp16(st + OFF_AH + so0, pAh + k0);  cp16(st + OFF_AH + so1, pAh + k0 + 8);
        cp16(st + OFF_AL + so0, pAl + k0);  cp16(st + OFF_AL + so1, pAl + k0 + 8);
        cp16(st + OFF_BH + so0, pBh + k0);  cp16(st + OFF_BH + so1, pBh + k0 + 8);
        cp16(st + OFF_BL + so0, pBl + k0);  cp16(st + OFF_BL + so1, pBl + k0 + 8);
    };

    // ---- compute setup: warp grid 4(m) x 2(n), warp tile 32x64 ------------
    const int lane = tid & 31;
    const int wid  = tid >> 5;
    const int wm   = wid & 3;
    const int wn   = wid >> 2;
    const int g    = lane >> 3;
    const int l7   = lane & 7;

    uint32_t aro[2], asz[2];
    #pragma unroll
    for (int mt = 0; mt < 2; mt++) {
        uint32_t rr = wm * 32 + mt * 16 + ((g & 1) << 3) + l7;
        aro[mt] = rr * 64u; asz[mt] = (rr >> 1) & 3u;
    }
    const uint32_t cbA = (uint32_t)(g >> 1);
    uint32_t bro[4], bsz[4];
    #pragma unroll
    for (int np = 0; np < 4; np++) {
        uint32_t rr = wn * 64 + np * 16 + ((g >> 1) << 3) + l7;
        bro[np] = rr * 64u; bsz[np] = (rr >> 1) & 3u;
    }
    const uint32_t cbB = (uint32_t)(g & 1);

    float acc[2][8][4];
    #pragma unroll
    for (int mt = 0; mt < 2; mt++)
        #pragma unroll
        for (int nt = 0; nt < 8; nt++)
            #pragma unroll
            for (int i = 0; i < 4; i++) acc[mt][nt][i] = 0.f;

    const int nch = K / 32;
    load_chunk(0, 0); CP_COMMIT();
    load_chunk(1, 1); CP_COMMIT();

    int slot = 0;
    for (int i = 0; i < nch; i++) {
        if (i == nch - 1) CP_WAIT(0);
        else              CP_WAIT(1);
        __syncthreads();
        if (i + 2 < nch) {
            int ns = slot + 2; if (ns >= 3) ns -= 3;
            load_chunk(i + 2, ns); CP_COMMIT();
        }

        uint32_t st = sbase + (uint32_t)slot * STAGE_BYTES;
        #pragma unroll
        for (int ks = 0; ks < 2; ks++) {
            uint32_t bh[4][4], bl[4][4];
            #pragma unroll
            for (int np = 0; np < 4; np++) {
                uint32_t off = bro[np] + ((((uint32_t)(ks << 1) + cbB) ^ bsz[np]) << 4);
                ldsm_x4(st + OFF_BH + off, bh[np]);
                ldsm_x4(st + OFF_BL + off, bl[np]);
            }
            #pragma unroll
            for (int mt = 0; mt < 2; mt++) {
                uint32_t ah[4], al[4];
                uint32_t off = aro[mt] + ((((uint32_t)(ks << 1) + cbA) ^ asz[mt]) << 4);
                ldsm_x4(st + OFF_AH + off, ah);
                ldsm_x4(st + OFF_AL + off, al);
                #pragma unroll
                for (int nt = 0; nt < 8; nt++)
                    mma16816(acc[mt][nt], ah, &bh[nt >> 1][(nt & 1) * 2]);
                #pragma unroll
                for (int nt = 0; nt < 8; nt++)
                    mma16816(acc[mt][nt], ah, &bl[nt >> 1][(nt & 1) * 2]);
                #pragma unroll
                for (int nt = 0; nt < 8; nt++)
                    mma16816(acc[mt][nt], al, &bh[nt >> 1][(nt & 1) * 2]);
            }
        }
        slot++; if (slot >= 3) slot -= 3;
    }

    // ---- epilogue ----
    const long zC = (long)z * sC;
    #pragma unroll
    for (int mt = 0; mt < 2; mt++)
        #pragma unroll
        for (int nt = 0; nt < 8; nt++) {
            int r0 = m0 + wm * 32 + mt * 16 + (lane >> 2);
            int c0 = n0 + wn * 64 + nt * 8 + (lane & 3) * 2;
            float v0 = alpha * acc[mt][nt][0], v1 = alpha * acc[mt][nt][1];
            float v2 = alpha * acc[mt][nt][2], v3 = alpha * acc[mt][nt][3];
            if (MODE == 0) {
                *(float2*)&C[zC + (long)r0 * N + c0]       = make_float2(v0, v1);
                *(float2*)&C[zC + (long)(r0 + 8) * N + c0] = make_float2(v2, v3);
            } else if (MODE == 1) {
                __nv_bfloat16 h0 = __float2bfloat16(v0), h1 = __float2bfloat16(v1);
                __nv_bfloat16 h2 = __float2bfloat16(v2), h3 = __float2bfloat16(v3);
                *(__nv_bfloat162*)&Ch[zC + (long)r0 * N + c0] = __nv_bfloat162(h0, h1);
                *(__nv_bfloat162*)&Ch[zC + (long)(r0 + 8) * N + c0] = __nv_bfloat162(h2, h3);
                __nv_bfloat16 q0 = __float2bfloat16(v0 - __bfloat162float(h0));
                __nv_bfloat16 q1 = __float2bfloat16(v1 - __bfloat162float(h1));
                __nv_bfloat16 q2 = __float2bfloat16(v2 - __bfloat162float(h2));
                __nv_bfloat16 q3 = __float2bfloat16(v3 - __bfloat162float(h3));
                *(__nv_bfloat162*)&Cl[zC + (long)r0 * N + c0] = __nv_bfloat162(q0, q1);
                *(__nv_bfloat162*)&Cl[zC + (long)(r0 + 8) * N + c0] = __nv_bfloat162(q2, q3);
            } else { // MODE 3
                if (z == 2) {
                    *(float2*)&C[(long)r0 * N + c0]       = make_float2(v0, v1);
                    *(float2*)&C[(long)(r0 + 8) * N + c0] = make_float2(v2, v3);
                } else {
                    __nv_bfloat16* hi = Ch + (long)z * NH;
                    __nv_bfloat16* lo = Cl + (long)z * NH;
                    int j  = c0 >> 1;
                    int sa = r0 & (SS - 1);
                    int sb = (r0 + 8) & (SS - 1);
                    float ca = Fc[(long)sa * DD2 + j], na = Fs[(long)sa * DD2 + j];
                    float cbb = Fc[(long)sb * DD2 + j], nb = Fs[(long)sb * DD2 + j];
                    float o0 = v0 * ca - v1 * na,  o1 = v0 * na + v1 * ca;
                    float o2 = v2 * cbb - v3 * nb, o3 = v2 * nb + v3 * cbb;
                    if (z == 1) {
                        *(float2*)&C1[(long)r0 * N + c0]       = make_float2(o0, o1);
                        *(float2*)&C1[(long)(r0 + 8) * N + c0] = make_float2(o2, o3);
                    }
                    __nv_bfloat16 h0 = __float2bfloat16(o0), h1 = __float2bfloat16(o1);
                    __nv_bfloat16 h2 = __float2bfloat16(o2), h3 = __float2bfloat16(o3);
                    *(__nv_bfloat162*)&hi[(long)r0 * N + c0] = __nv_bfloat162(h0, h1);
                    *(__nv_bfloat162*)&hi[(long)(r0 + 8) * N + c0] = __nv_bfloat162(h2, h3);
                    __nv_bfloat16 q0 = __float2bfloat16(o0 - __bfloat162float(h0));
                    __nv_bfloat16 q1 = __float2bfloat16(o1 - __bfloat162float(h1));
                    __nv_bfloat16 q2 = __float2bfloat16(o2 - __bfloat162float(h2));
                    __nv_bfloat16 q3 = __float2bfloat16(o3 - __bfloat162float(h3));
                    *(__nv_bfloat162*)&lo[(long)r0 * N + c0] = __nv_bfloat162(q0, q1);
                    *(__nv_bfloat162*)&lo[(long)(r0 + 8) * N + c0] = __nv_bfloat162(q2, q3);
                }
            }
        }
}

// ---------------- split hs: x -> (bf16 hi, bf16 lo) ------------------------
__global__ __launch_bounds__(256)
void split_kernel(const float* __restrict__ x, __nv_bfloat16* __restrict__ hi,
                  __nv_bfloat16* __restrict__ lo, long n)
{
    long i = ((long)blockIdx.x * 256 + threadIdx.x) * 4;
    if (i >= n) return;
    float4 v = *(const float4*)&x[i];
    __nv_bfloat16 h0 = __float2bfloat16(v.x), h1 = __float2bfloat16(v.y);
    __nv_bfloat16 h2 = __float2bfloat16(v.z), h3 = __float2bfloat16(v.w);
    __nv_bfloat16 l0 = __float2bfloat16(v.x - __bfloat162float(h0));
    __nv_bfloat16 l1 = __float2bfloat16(v.y - __bfloat162float(h1));
    __nv_bfloat16 l2 = __float2bfloat16(v.z - __bfloat162float(h2));
    __nv_bfloat16 l3 = __float2bfloat16(v.w - __bfloat162float(h3));
    ((__nv_bfloat162*)&hi[i])[0] = __nv_bfloat162(h0, h1);
    ((__nv_bfloat162*)&hi[i])[1] = __nv_bfloat162(h2, h3);
    ((__nv_bfloat162*)&lo[i])[0] = __nv_bfloat162(l0, l1);
    ((__nv_bfloat162*)&lo[i])[1] = __nv_bfloat162(l2, l3);
}

// ---------------- split all 4 weights; wq/wk get row permutation -----------
// grid.y: 0=wq(perm), 1=wk(perm), 2=wv, 3=wo.  perm(o) = o<1024 ? 2o : 2(o-1024)+1
__global__ __launch_bounds__(256)
void split_w_kernel(const float* __restrict__ wq, const float* __restrict__ wk,
                    const float* __restrict__ wv, const float* __restrict__ wo,
                    __nv_bfloat16* __restrict__ WH, __nv_bfloat16* __restrict__ WL)
{
    int which = blockIdx.y;
    long i = ((long)blockIdx.x * 256 + threadIdx.x) * 4;
    if (i >= WN) return;
    const float* src = (which == 0) ? wq : (which == 1) ? wk : (which == 2) ? wv : wo;
    float4 v = *(const float4*)&src[i];
    long d;
    if (which < 2) {
        int  o = (int)(i >> 11);            // row (output dim)
        long h = i & (HH - 1);
        int po = (o < DD2) ? (o << 1) : (((o - DD2) << 1) | 1);
        d = (long)which * WN + (long)po * HH + h;
    } else {
        d = (long)which * WN + i;
    }
    __nv_bfloat16 h0 = __float2bfloat16(v.x), h1 = __float2bfloat16(v.y);
    __nv_bfloat16 h2 = __float2bfloat16(v.z), h3 = __float2bfloat16(v.w);
    __nv_bfloat16 l0 = __float2bfloat16(v.x - __bfloat162float(h0));
    __nv_bfloat16 l1 = __float2bfloat16(v.y - __bfloat162float(h1));
    __nv_bfloat16 l2 = __float2bfloat16(v.z - __bfloat162float(h2));
    __nv_bfloat16 l3 = __float2bfloat16(v.w - __bfloat162float(h3));
    ((__nv_bfloat162*)&WH[d])[0] = __nv_bfloat162(h0, h1);
    ((__nv_bfloat162*)&WH[d])[1] = __nv_bfloat162(h2, h3);
    ((__nv_bfloat162*)&WL[d])[0] = __nv_bfloat162(l0, l1);
    ((__nv_bfloat162*)&WL[d])[1] = __nv_bfloat162(l2, l3);
}

// ---------------- transpose + split: V[b][s][h] -> Vt[b][h][s] -------------
__global__ __launch_bounds__(256)
void transpose_split_kernel(const float* __restrict__ V, __nv_bfloat16* __restrict__ hi,
                            __nv_bfloat16* __restrict__ lo)
{
    __shared__ float t[32][33];
    int b = blockIdx.z;
    int s0 = blockIdx.x * 32, h0 = blockIdx.y * 32;
    const float* Vb = V + (long)b * SS * HH;
    #pragma unroll
    for (int r = 0; r < 4; r++)
        t[threadIdx.y + r * 8][threadIdx.x] =
            Vb[(long)(s0 + threadIdx.y + r * 8) * HH + h0 + threadIdx.x];
    __syncthreads();
    #pragma unroll
    for (int r = 0; r < 4; r++) {
        int h = h0 + threadIdx.y + r * 8;
        float v = t[threadIdx.x][threadIdx.y + r * 8];
        __nv_bfloat16 hh = __float2bfloat16(v);
        __nv_bfloat16 ll = __float2bfloat16(v - __bfloat162float(hh));
        long o = (long)b * HH * SS + (long)h * SS + s0 + threadIdx.x;
        hi[o] = hh; lo[o] = ll;
    }
}

// ---------------- fused softmax + split ------------------------------------
__global__ __launch_bounds__(256)
void softmax_split_kernel(const float* __restrict__ sc,
                          __nv_bfloat16* __restrict__ ph, __nv_bfloat16* __restrict__ pl)
{
    const float* p = sc + (size_t)blockIdx.x * SS;
    __nv_bfloat16* oh = ph + (size_t)blockIdx.x * SS;
    __nv_bfloat16* ol = pl + (size_t)blockIdx.x * SS;
    const int tid = threadIdx.x;
    float4 v[4];
    float lmax = -3.0e38f;
    #pragma unroll
    for (int i = 0; i < 4; i++) {
        v[i] = ((const float4*)p)[tid + i * 256];
        lmax = fmaxf(lmax, fmaxf(fmaxf(v[i].x, v[i].y), fmaxf(v[i].z, v[i].w)));
    }
    __shared__ float redmax[8], redsum[8];
    #pragma unroll
    for (int o = 16; o > 0; o >>= 1) lmax = fmaxf(lmax, __shfl_xor_sync(~0u, lmax, o));
    if ((tid & 31) == 0) redmax[tid >> 5] = lmax;
    __syncthreads();
    float bmax = redmax[0];
    #pragma unroll
    for (int w = 1; w < 8; w++) bmax = fmaxf(bmax, redmax[w]);
    float lsum = 0.f;
    #pragma unroll
    for (int i = 0; i < 4; i++) {
        v[i].x = __expf(v[i].x - bmax); v[i].y = __expf(v[i].y - bmax);
        v[i].z = __expf(v[i].z - bmax); v[i].w = __expf(v[i].w - bmax);
        lsum += v[i].x + v[i].y + v[i].z + v[i].w;
    }
    #pragma unroll
    for (int o = 16; o > 0; o >>= 1) lsum += __shfl_xor_sync(~0u, lsum, o);
    if ((tid & 31) == 0) redsum[tid >> 5] = lsum;
    __syncthreads();
    float bsum = 0.f;
    #pragma unroll
    for (int w = 0; w < 8; w++) bsum += redsum[w];
    float rinv = 1.f / bsum;
    #pragma unroll
    for (int i = 0; i < 4; i++) {
        float a0 = v[i].x * rinv, a1 = v[i].y * rinv, a2 = v[i].z * rinv, a3 = v[i].w * rinv;
        int base = (tid + i * 256) * 4;
        __nv_bfloat16 h0 = __float2bfloat16(a0), h1 = __float2bfloat16(a1);
        __nv_bfloat16 h2 = __float2bfloat16(a2), h3 = __float2bfloat16(a3);
        ((__nv_bfloat162*)&oh[base])[0] = __nv_bfloat162(h0, h1);
        ((__nv_bfloat162*)&oh[base])[1] = __nv_bfloat162(h2, h3);
        __nv_bfloat16 l0 = __float2bfloat16(a0 - __bfloat162float(h0));
        __nv_bfloat16 l1 = __float2bfloat16(a1 - __bfloat162float(h1));
        __nv_bfloat16 l2 = __float2bfloat16(a2 - __bfloat162float(h2));
        __nv_bfloat16 l3 = __float2bfloat16(a3 - __bfloat162float(h3));
        ((__nv_bfloat162*)&ol[base])[0] = __nv_bfloat162(l0, l1);
        ((__nv_bfloat162*)&ol[base])[1] = __nv_bfloat162(l2, l3);
    }
}

// ---------------------------------------------------------------------------
extern "C" void kernel_launch(void* const* d_in, const int* in_sizes, int n_in,
                              void* d_out, int out_size)
{
    (void)in_sizes; (void)n_in; (void)out_size;
    const float* hs   = (const float*)d_in[0];
    const float* wq   = (const float*)d_in[1];
    const float* wk   = (const float*)d_in[2];
    const float* wv   = (const float*)d_in[3];
    const float* wo   = (const float*)d_in[4];
    const float* fcos = (const float*)d_in[5];
    const float* fsin = (const float*)d_in[6];

    float* out      = (float*)d_out;
    float* out_krot = out + NH;
    float* out_v    = out + 2 * NH;

    float *sc;
    __nv_bfloat16 *hsh, *hsl, *wh, *wl, *qkh, *qkl, *ph, *pl, *vth, *vtl, *cxh, *cxl;
    cudaGetSymbolAddress((void**)&sc,  g_scores);
    cudaGetSymbolAddress((void**)&hsh, g_hs_h);   cudaGetSymbolAddress((void**)&hsl, g_hs_l);
    cudaGetSymbolAddress((void**)&wh,  g_w_h);    cudaGetSymbolAddress((void**)&wl,  g_w_l);
    cudaGetSymbolAddress((void**)&qkh, g_qkr_h);  cudaGetSymbolAddress((void**)&qkl, g_qkr_l);
    cudaGetSymbolAddress((void**)&ph,  g_p_h);    cudaGetSymbolAddress((void**)&pl,  g_p_l);
    cudaGetSymbolAddress((void**)&vth, g_vt_h);   cudaGetSymbolAddress((void**)&vtl, g_vt_l);
    cudaGetSymbolAddress((void**)&cxh, g_cx_h);   cudaGetSymbolAddress((void**)&cxl, g_cx_l);

    cudaFuncSetAttribute(gemm_bf16x3<0>, cudaFuncAttributeMaxDynamicSharedMemorySize, GEMM_SMEM);
    cudaFuncSetAttribute(gemm_bf16x3<1>, cudaFuncAttributeMaxDynamicSharedMemorySize, GEMM_SMEM);
    cudaFuncSetAttribute(gemm_bf16x3<3>, cudaFuncAttributeMaxDynamicSharedMemorySize, GEMM_SMEM);

    // 0) split inputs (hs; 4 weights in one launch, wq/wk row-permuted)
    split_kernel<<<(unsigned)((NH / 4 + 255) / 256), 256>>>(hs, hsh, hsl, NH);
    dim3 gW((unsigned)((WN / 4 + 255) / 256), 4);
    split_w_kernel<<<gW, 256>>>(wq, wk, wv, wo, wh, wl);

    // 1) QKV merged + fused RoPE epilogue:
    //    z=0: q_rot hi/lo ; z=1: k_rot fp32 (output) + hi/lo ; z=2: v fp32 (output)
    dim3 gQKV(HH / 128, NR / 128, 3);
    gemm_bf16x3<3><<<gQKV, 256, GEMM_SMEM>>>(hsh, hsl, wh, wl,
                                             out_v, out_krot, qkh, qkl,
                                             fcos, fsin, NR, HH, HH, 0, WN, 0, 1.f);

    // 2) scores = 0.125 * Qr Kr^T  (batched)
    dim3 gS(SS / 128, SS / 128, BB);
    gemm_bf16x3<0><<<gS, 256, GEMM_SMEM>>>(qkh, qkl, qkh + NH, qkl + NH, sc, nullptr,
                                           nullptr, nullptr, nullptr, nullptr, SS, SS, HH,
                                           (long)SS * HH, (long)SS * HH, (long)SS * SS, ATT_SCALE);

    // 3) fused softmax + split -> P hi/lo
    softmax_split_kernel<<<NR, 256>>>(sc, ph, pl);

    // 4) V transpose + split
    dim3 gT(SS / 32, HH / 32, BB);
    transpose_split_kernel<<<gT, dim3(32, 8)>>>(out_v, vth, vtl);

    // 5) ctx = P @ V^T -> split epilogue directly to cx hi/lo
    dim3 gC(HH / 128, SS / 128, BB);
    gemm_bf16x3<1><<<gC, 256, GEMM_SMEM>>>(ph, pl, vth, vtl, nullptr, nullptr,
                                           cxh, cxl, nullptr, nullptr, SS, HH, SS,
                                           (long)SS * SS, (long)HH * SS, (long)SS * HH, 1.f);

    // 6) output projection
    dim3 gO(HH / 128, NR / 128, 1);
    gemm_bf16x3<0><<<gO, 256, GEMM_SMEM>>>(cxh, cxl, wh + 3 * WN, wl + 3 * WN, out, nullptr,
                                           nullptr, nullptr, nullptr, nullptr,
                                           NR, HH, HH, 0, 0, 0, 1.f);
}

// round 14
// speedup vs baseline: 5.7010x; 1.0823x over previous
#include <cuda_runtime.h>
#include <cuda_bf16.h>
#include <cuda_fp16.h>
#include <cstdint>

#define BB 2
#define SS 4096
#define HH 2048
#define DD2 1024
#define NR (BB*SS)            // 8192
#define NH ((long)NR*HH)      // 16,777,216
#define NSCORE ((long)BB*SS*SS)
#define ATT_SCALE 0.125f
#define WN ((long)HH*HH)

// ---------------- scratch (__device__ globals; no allocs allowed) ----------
__device__ float g_scores[NSCORE];

__device__ __nv_bfloat16 g_hs_h[NH],  g_hs_l[NH];
__device__ __nv_bfloat16 g_w_h[4L*HH*HH], g_w_l[4L*HH*HH];
__device__ __nv_bfloat16 g_qkr_h[2*NH], g_qkr_l[2*NH];   // q_rot | k_rot hi/lo
__device__ __half        g_p16[NSCORE];                  // P as single fp16
__device__ __half        g_vt16_h[NH], g_vt16_l[NH];     // V^T fp16 hi/lo
__device__ __nv_bfloat16 g_cx_h[NH], g_cx_l[NH];

// ---------------- PTX helpers (base sm_103 ISA only) -----------------------
__device__ __forceinline__ uint32_t smem_u32(const void* p) {
    uint32_t a;
    asm("{ .reg .u64 t; cvta.to.shared.u64 t, %1; cvt.u32.u64 %0, t; }" : "=r"(a) : "l"(p));
    return a;
}
#define CP_COMMIT()  asm volatile("cp.async.commit_group;" ::: "memory")
#define CP_WAIT(n)   asm volatile("cp.async.wait_group %0;" :: "n"(n) : "memory")

__device__ __forceinline__ void cp16(uint32_t dst, const void* src) {
    asm volatile("cp.async.cg.shared.global [%0], [%1], 16;"
                 :: "r"(dst), "l"(__cvta_generic_to_global(src)) : "memory");
}
__device__ __forceinline__ void ldsm_x4(uint32_t addr, uint32_t* r) {
    asm volatile("ldmatrix.sync.aligned.m8n8.x4.shared.b16 {%0,%1,%2,%3}, [%4];"
        : "=r"(r[0]), "=r"(r[1]), "=r"(r[2]), "=r"(r[3]) : "r"(addr));
}
__device__ __forceinline__ void mma_bf16(float* d, const uint32_t* a, const uint32_t* b) {
    asm volatile("mma.sync.aligned.m16n8k16.row.col.f32.bf16.bf16.f32 "
        "{%0,%1,%2,%3}, {%4,%5,%6,%7}, {%8,%9}, {%0,%1,%2,%3};"
        : "+f"(d[0]), "+f"(d[1]), "+f"(d[2]), "+f"(d[3])
        : "r"(a[0]), "r"(a[1]), "r"(a[2]), "r"(a[3]), "r"(b[0]), "r"(b[1]));
}
__device__ __forceinline__ void mma_fp16(float* d, const uint32_t* a, const uint32_t* b) {
    asm volatile("mma.sync.aligned.m16n8k16.row.col.f32.f16.f16.f32 "
        "{%0,%1,%2,%3}, {%4,%5,%6,%7}, {%8,%9}, {%0,%1,%2,%3};"
        : "+f"(d[0]), "+f"(d[1]), "+f"(d[2]), "+f"(d[3])
        : "r"(a[0]), "r"(a[1]), "r"(a[2]), "r"(a[3]), "r"(b[0]), "r"(b[1]));
}

// SMEM tile rows are 64B (32 elems = 4 16B chunks); chunk' = chunk ^ ((row>>1)&3)
__device__ __forceinline__ uint32_t swz(uint32_t row, uint32_t chunk) {
    return row * 64u + ((chunk ^ ((row >> 1) & 3u)) << 4);
}

// -------- split-precision HMMA GEMM: 128x128 tile, BK=32, 3 stages ---------
// MODE 0: C fp32.
// MODE 1: (Ch,Cl) bf16 hi/lo split of acc.
// MODE 3: merged QKV+RoPE (z=0 q_rot hi/lo; z=1 k_rot fp32+hi/lo; z=2 v fp32).
// TERMS 3: acc = Ah*Bh + Ah*Bl + Al*Bh.   TERMS 2: acc = Ah*Bh + Ah*Bl.
// FMT 0: bf16 operands.  FMT 1: fp16 operands.
#define PARTB 8192

template<int MODE, int TERMS, int FMT>
__global__ __launch_bounds__(256, 2)
void gemm_split(const __nv_bfloat16* __restrict__ Ahi, const __nv_bfloat16* __restrict__ Alo,
                const __nv_bfloat16* __restrict__ Bhi, const __nv_bfloat16* __restrict__ Blo,
                float* __restrict__ C, float* __restrict__ C1,
                __nv_bfloat16* __restrict__ Ch, __nv_bfloat16* __restrict__ Cl,
                const float* __restrict__ Fc, const float* __restrict__ Fs,
                int M, int N, int K, long sA, long sB, long sC, float alpha)
{
    constexpr uint32_t OFF_AH = 0;
    constexpr uint32_t OFF_AL = PARTB;                      // only if TERMS==3
    constexpr uint32_t OFF_BH = (TERMS == 3) ? 2*PARTB : PARTB;
    constexpr uint32_t OFF_BL = (TERMS == 3) ? 3*PARTB : 2*PARTB;
    constexpr uint32_t STAGE  = (TERMS == 3) ? 4*PARTB : 3*PARTB;

    extern __shared__ char smem[];
    const uint32_t sbase = smem_u32(smem);
    const int tid = threadIdx.x;
    const int z = blockIdx.z;
    Ahi += (long)z * sA;  if (TERMS == 3) Alo += (long)z * sA;
    Bhi += (long)z * sB;  Blo += (long)z * sB;
    const int m0 = blockIdx.y * 128;
    const int n0 = blockIdx.x * 128;

    const int r  = tid >> 1;
    const int cb = (tid & 1) * 2;
    const __nv_bfloat16* pAh = Ahi + (long)(m0 + r) * K;
    const __nv_bfloat16* pAl = (TERMS == 3) ? (Alo + (long)(m0 + r) * K) : nullptr;
    const __nv_bfloat16* pBh = Bhi + (long)(n0 + r) * K;
    const __nv_bfloat16* pBl = Blo + (long)(n0 + r) * K;
    const uint32_t so0 = swz((uint32_t)r, (uint32_t)cb);
    const uint32_t so1 = swz((uint32_t)r, (uint32_t)cb + 1);

    auto load_chunk = [&](int j, int slot) {
        uint32_t st = sbase + (uint32_t)slot * STAGE;
        long k0 = (long)j * 32 + (long)cb * 8;
        cp16(st + OFF_AH + so0, pAh + k0);  cp16(st + OFF_AH + so1, pAh + k0 + 8);
        if (TERMS == 3) {
            cp16(st + OFF_AL + so0, pAl + k0);  cp16(st + OFF_AL + so1, pAl + k0 + 8);
        }
        cp16(st + OFF_BH + so0, pBh + k0);  cp16(st + OFF_BH + so1, pBh + k0 + 8);
        cp16(st + OFF_BL + so0, pBl + k0);  cp16(st + OFF_BL + so1, pBl + k0 + 8);
    };

    const int lane = tid & 31;
    const int wid  = tid >> 5;
    const int wm   = wid & 3;
    const int wn   = wid >> 2;
    const int g    = lane >> 3;
    const int l7   = lane & 7;

    uint32_t aro[2], asz[2];
    #pragma unroll
    for (int mt = 0; mt < 2; mt++) {
        uint32_t rr = wm * 32 + mt * 16 + ((g & 1) << 3) + l7;
        aro[mt] = rr * 64u; asz[mt] = (rr >> 1) & 3u;
    }
    const uint32_t cbA = (uint32_t)(g >> 1);
    uint32_t bro[4], bsz[4];
    #pragma unroll
    for (int np = 0; np < 4; np++) {
        uint32_t rr = wn * 64 + np * 16 + ((g >> 1) << 3) + l7;
        bro[np] = rr * 64u; bsz[np] = (rr >> 1) & 3u;
    }
    const uint32_t cbB = (uint32_t)(g & 1);

    float acc[2][8][4];
    #pragma unroll
    for (int mt = 0; mt < 2; mt++)
        #pragma unroll
        for (int nt = 0; nt < 8; nt++)
            #pragma unroll
            for (int i = 0; i < 4; i++) acc[mt][nt][i] = 0.f;

    const int nch = K / 32;
    load_chunk(0, 0); CP_COMMIT();
    load_chunk(1, 1); CP_COMMIT();

    int slot = 0;
    for (int i = 0; i < nch; i++) {
        if (i == nch - 1) CP_WAIT(0);
        else              CP_WAIT(1);
        __syncthreads();
        if (i + 2 < nch) {
            int ns = slot + 2; if (ns >= 3) ns -= 3;
            load_chunk(i + 2, ns); CP_COMMIT();
        }

        uint32_t st = sbase + (uint32_t)slot * STAGE;
        #pragma unroll
        for (int ks = 0; ks < 2; ks++) {
            uint32_t bh[4][4], bl[4][4];
            #pragma unroll
            for (int np = 0; np < 4; np++) {
                uint32_t off = bro[np] + ((((uint32_t)(ks << 1) + cbB) ^ bsz[np]) << 4);
                ldsm_x4(st + OFF_BH + off, bh[np]);
                ldsm_x4(st + OFF_BL + off, bl[np]);
            }
            #pragma unroll
            for (int mt = 0; mt < 2; mt++) {
                uint32_t ah[4], al[4];
                uint32_t off = aro[mt] + ((((uint32_t)(ks << 1) + cbA) ^ asz[mt]) << 4);
                ldsm_x4(st + OFF_AH + off, ah);
                if (TERMS == 3) ldsm_x4(st + OFF_AL + off, al);
                #pragma unroll
                for (int nt = 0; nt < 8; nt++) {
                    if (FMT == 0) mma_bf16(acc[mt][nt], ah, &bh[nt >> 1][(nt & 1) * 2]);
                    else          mma_fp16(acc[mt][nt], ah, &bh[nt >> 1][(nt & 1) * 2]);
                }
                #pragma unroll
                for (int nt = 0; nt < 8; nt++) {
                    if (FMT == 0) mma_bf16(acc[mt][nt], ah, &bl[nt >> 1][(nt & 1) * 2]);
                    else          mma_fp16(acc[mt][nt], ah, &bl[nt >> 1][(nt & 1) * 2]);
                }
                if (TERMS == 3) {
                    #pragma unroll
                    for (int nt = 0; nt < 8; nt++) {
                        if (FMT == 0) mma_bf16(acc[mt][nt], al, &bh[nt >> 1][(nt & 1) * 2]);
                        else          mma_fp16(acc[mt][nt], al, &bh[nt >> 1][(nt & 1) * 2]);
                    }
                }
            }
        }
        slot++; if (slot >= 3) slot -= 3;
    }

    // ---- epilogue ----
    const long zC = (long)z * sC;
    #pragma unroll
    for (int mt = 0; mt < 2; mt++)
        #pragma unroll
        for (int nt = 0; nt < 8; nt++) {
            int r0 = m0 + wm * 32 + mt * 16 + (lane >> 2);
            int c0 = n0 + wn * 64 + nt * 8 + (lane & 3) * 2;
            float v0 = alpha * acc[mt][nt][0], v1 = alpha * acc[mt][nt][1];
            float v2 = alpha * acc[mt][nt][2], v3 = alpha * acc[mt][nt][3];
            if (MODE == 0) {
                *(float2*)&C[zC + (long)r0 * N + c0]       = make_float2(v0, v1);
                *(float2*)&C[zC + (long)(r0 + 8) * N + c0] = make_float2(v2, v3);
            } else if (MODE == 1) {
                __nv_bfloat16 h0 = __float2bfloat16(v0), h1 = __float2bfloat16(v1);
                __nv_bfloat16 h2 = __float2bfloat16(v2), h3 = __float2bfloat16(v3);
                *(__nv_bfloat162*)&Ch[zC + (long)r0 * N + c0] = __nv_bfloat162(h0, h1);
                *(__nv_bfloat162*)&Ch[zC + (long)(r0 + 8) * N + c0] = __nv_bfloat162(h2, h3);
                __nv_bfloat16 q0 = __float2bfloat16(v0 - __bfloat162float(h0));
                __nv_bfloat16 q1 = __float2bfloat16(v1 - __bfloat162float(h1));
                __nv_bfloat16 q2 = __float2bfloat16(v2 - __bfloat162float(h2));
                __nv_bfloat16 q3 = __float2bfloat16(v3 - __bfloat162float(h3));
                *(__nv_bfloat162*)&Cl[zC + (long)r0 * N + c0] = __nv_bfloat162(q0, q1);
                *(__nv_bfloat162*)&Cl[zC + (long)(r0 + 8) * N + c0] = __nv_bfloat162(q2, q3);
            } else { // MODE 3
                if (z == 2) {
                    *(float2*)&C[(long)r0 * N + c0]       = make_float2(v0, v1);
                    *(float2*)&C[(long)(r0 + 8) * N + c0] = make_float2(v2, v3);
                } else {
                    __nv_bfloat16* hi = Ch + (long)z * NH;
                    __nv_bfloat16* lo = Cl + (long)z * NH;
                    int j  = c0 >> 1;
                    int sa = r0 & (SS - 1);
                    int sb = (r0 + 8) & (SS - 1);
                    float ca = Fc[(long)sa * DD2 + j], na = Fs[(long)sa * DD2 + j];
                    float cbb = Fc[(long)sb * DD2 + j], nb = Fs[(long)sb * DD2 + j];
                    float o0 = v0 * ca - v1 * na,  o1 = v0 * na + v1 * ca;
                    float o2 = v2 * cbb - v3 * nb, o3 = v2 * nb + v3 * cbb;
                    if (z == 1) {
                        *(float2*)&C1[(long)r0 * N + c0]       = make_float2(o0, o1);
                        *(float2*)&C1[(long)(r0 + 8) * N + c0] = make_float2(o2, o3);
                    }
                    __nv_bfloat16 h0 = __float2bfloat16(o0), h1 = __float2bfloat16(o1);
                    __nv_bfloat16 h2 = __float2bfloat16(o2), h3 = __float2bfloat16(o3);
                    *(__nv_bfloat162*)&hi[(long)r0 * N + c0] = __nv_bfloat162(h0, h1);
                    *(__nv_bfloat162*)&hi[(long)(r0 + 8) * N + c0] = __nv_bfloat162(h2, h3);
                    __nv_bfloat16 q0 = __float2bfloat16(o0 - __bfloat162float(h0));
                    __nv_bfloat16 q1 = __float2bfloat16(o1 - __bfloat162float(h1));
                    __nv_bfloat16 q2 = __float2bfloat16(o2 - __bfloat162float(h2));
                    __nv_bfloat16 q3 = __float2bfloat16(o3 - __bfloat162float(h3));
                    *(__nv_bfloat162*)&lo[(long)r0 * N + c0] = __nv_bfloat162(q0, q1);
                    *(__nv_bfloat162*)&lo[(long)(r0 + 8) * N + c0] = __nv_bfloat162(q2, q3);
                }
            }
        }
}

// ---------------- split hs: x -> (bf16 hi, bf16 lo) ------------------------
__global__ __launch_bounds__(256)
void split_kernel(const float* __restrict__ x, __nv_bfloat16* __restrict__ hi,
                  __nv_bfloat16* __restrict__ lo, long n)
{
    long i = ((long)blockIdx.x * 256 + threadIdx.x) * 4;
    if (i >= n) return;
    float4 v = *(const float4*)&x[i];
    __nv_bfloat16 h0 = __float2bfloat16(v.x), h1 = __float2bfloat16(v.y);
    __nv_bfloat16 h2 = __float2bfloat16(v.z), h3 = __float2bfloat16(v.w);
    __nv_bfloat16 l0 = __float2bfloat16(v.x - __bfloat162float(h0));
    __nv_bfloat16 l1 = __float2bfloat16(v.y - __bfloat162float(h1));
    __nv_bfloat16 l2 = __float2bfloat16(v.z - __bfloat162float(h2));
    __nv_bfloat16 l3 = __float2bfloat16(v.w - __bfloat162float(h3));
    ((__nv_bfloat162*)&hi[i])[0] = __nv_bfloat162(h0, h1);
    ((__nv_bfloat162*)&hi[i])[1] = __nv_bfloat162(h2, h3);
    ((__nv_bfloat162*)&lo[i])[0] = __nv_bfloat162(l0, l1);
    ((__nv_bfloat162*)&lo[i])[1] = __nv_bfloat162(l2, l3);
}

// ---------------- split all 4 weights; wq/wk get row permutation -----------
__global__ __launch_bounds__(256)
void split_w_kernel(const float* __restrict__ wq, const float* __restrict__ wk,
                    const float* __restrict__ wv, const float* __restrict__ wo,
                    __nv_bfloat16* __restrict__ WH, __nv_bfloat16* __restrict__ WL)
{
    int which = blockIdx.y;
    long i = ((long)blockIdx.x * 256 + threadIdx.x) * 4;
    if (i >= WN) return;
    const float* src = (which == 0) ? wq : (which == 1) ? wk : (which == 2) ? wv : wo;
    float4 v = *(const float4*)&src[i];
    long d;
    if (which < 2) {
        int  o = (int)(i >> 11);
        long h = i & (HH - 1);
        int po = (o < DD2) ? (o << 1) : (((o - DD2) << 1) | 1);
        d = (long)which * WN + (long)po * HH + h;
    } else {
        d = (long)which * WN + i;
    }
    __nv_bfloat16 h0 = __float2bfloat16(v.x), h1 = __float2bfloat16(v.y);
    __nv_bfloat16 h2 = __float2bfloat16(v.z), h3 = __float2bfloat16(v.w);
    __nv_bfloat16 l0 = __float2bfloat16(v.x - __bfloat162float(h0));
    __nv_bfloat16 l1 = __float2bfloat16(v.y - __bfloat162float(h1));
    __nv_bfloat16 l2 = __float2bfloat16(v.z - __bfloat162float(h2));
    __nv_bfloat16 l3 = __float2bfloat16(v.w - __bfloat162float(h3));
    ((__nv_bfloat162*)&WH[d])[0] = __nv_bfloat162(h0, h1);
    ((__nv_bfloat162*)&WH[d])[1] = __nv_bfloat162(h2, h3);
    ((__nv_bfloat162*)&WL[d])[0] = __nv_bfloat162(l0, l1);
    ((__nv_bfloat162*)&WL[d])[1] = __nv_bfloat162(l2, l3);
}

// ---------------- transpose + split fp16: V[b][s][h] -> Vt[b][h][s] --------
__global__ __launch_bounds__(256)
void transpose_split16_kernel(const float* __restrict__ V, __half* __restrict__ hi,
                              __half* __restrict__ lo)
{
    __shared__ float t[32][33];
    int b = blockIdx.z;
    int s0 = blockIdx.x * 32, h0 = blockIdx.y * 32;
    const float* Vb = V + (long)b * SS * HH;
    #pragma unroll
    for (int r = 0; r < 4; r++)
        t[threadIdx.y + r * 8][threadIdx.x] =
            Vb[(long)(s0 + threadIdx.y + r * 8) * HH + h0 + threadIdx.x];
    __syncthreads();
    #pragma unroll
    for (int r = 0; r < 4; r++) {
        int h = h0 + threadIdx.y + r * 8;
        float v = t[threadIdx.x][threadIdx.y + r * 8];
        __half hh = __float2half_rn(v);
        __half ll = __float2half_rn(v - __half2float(hh));
        long o = (long)b * HH * SS + (long)h * SS + s0 + threadIdx.x;
        hi[o] = hh; lo[o] = ll;
    }
}

// ---------------- fused softmax -> single fp16 P ---------------------------
__global__ __launch_bounds__(256)
void softmax_fp16_kernel(const float* __restrict__ sc, __half* __restrict__ p16)
{
    const float* p = sc + (size_t)blockIdx.x * SS;
    __half* op = p16 + (size_t)blockIdx.x * SS;
    const int tid = threadIdx.x;
    float4 v[4];
    float lmax = -3.0e38f;
    #pragma unroll
    for (int i = 0; i < 4; i++) {
        v[i] = ((const float4*)p)[tid + i * 256];
        lmax = fmaxf(lmax, fmaxf(fmaxf(v[i].x, v[i].y), fmaxf(v[i].z, v[i].w)));
    }
    __shared__ float redmax[8], redsum[8];
    #pragma unroll
    for (int o = 16; o > 0; o >>= 1) lmax = fmaxf(lmax, __shfl_xor_sync(~0u, lmax, o));
    if ((tid & 31) == 0) redmax[tid >> 5] = lmax;
    __syncthreads();
    float bmax = redmax[0];
    #pragma unroll
    for (int w = 1; w < 8; w++) bmax = fmaxf(bmax, redmax[w]);
    float lsum = 0.f;
    #pragma unroll
    for (int i = 0; i < 4; i++) {
        v[i].x = __expf(v[i].x - bmax); v[i].y = __expf(v[i].y - bmax);
        v[i].z = __expf(v[i].z - bmax); v[i].w = __expf(v[i].w - bmax);
        lsum += v[i].x + v[i].y + v[i].z + v[i].w;
    }
    #pragma unroll
    for (int o = 16; o > 0; o >>= 1) lsum += __shfl_xor_sync(~0u, lsum, o);
    if ((tid & 31) == 0) redsum[tid >> 5] = lsum;
    __syncthreads();
    float bsum = 0.f;
    #pragma unroll
    for (int w = 0; w < 8; w++) bsum += redsum[w];
    float rinv = 1.f / bsum;
    #pragma unroll
    for (int i = 0; i < 4; i++) {
        float a0 = v[i].x * rinv, a1 = v[i].y * rinv, a2 = v[i].z * rinv, a3 = v[i].w * rinv;
        int base = (tid + i * 256) * 4;
        __half2 h01 = __floats2half2_rn(a0, a1);
        __half2 h23 = __floats2half2_rn(a2, a3);
        ((__half2*)&op[base])[0] = h01;
        ((__half2*)&op[base])[1] = h23;
    }
}

// ---------------------------------------------------------------------------
extern "C" void kernel_launch(void* const* d_in, const int* in_sizes, int n_in,
                              void* d_out, int out_size)
{
    (void)in_sizes; (void)n_in; (void)out_size;
    const float* hs   = (const float*)d_in[0];
    const float* wq   = (const float*)d_in[1];
    const float* wk   = (const float*)d_in[2];
    const float* wv   = (const float*)d_in[3];
    const float* wo   = (const float*)d_in[4];
    const float* fcos = (const float*)d_in[5];
    const float* fsin = (const float*)d_in[6];

    float* out      = (float*)d_out;
    float* out_krot = out + NH;
    float* out_v    = out + 2 * NH;

    float *sc;
    __nv_bfloat16 *hsh, *hsl, *wh, *wl, *qkh, *qkl, *cxh, *cxl;
    __half *p16, *vth, *vtl;
    cudaGetSymbolAddress((void**)&sc,  g_scores);
    cudaGetSymbolAddress((void**)&hsh, g_hs_h);   cudaGetSymbolAddress((void**)&hsl, g_hs_l);
    cudaGetSymbolAddress((void**)&wh,  g_w_h);    cudaGetSymbolAddress((void**)&wl,  g_w_l);
    cudaGetSymbolAddress((void**)&qkh, g_qkr_h);  cudaGetSymbolAddress((void**)&qkl, g_qkr_l);
    cudaGetSymbolAddress((void**)&p16, g_p16);
    cudaGetSymbolAddress((void**)&vth, g_vt16_h); cudaGetSymbolAddress((void**)&vtl, g_vt16_l);
    cudaGetSymbolAddress((void**)&cxh, g_cx_h);   cudaGetSymbolAddress((void**)&cxl, g_cx_l);

    const int SMEM3 = 3 * 4 * PARTB;   // 98304
    const int SMEM2 = 3 * 3 * PARTB;   // 73728
    cudaFuncSetAttribute(gemm_split<3,3,0>, cudaFuncAttributeMaxDynamicSharedMemorySize, SMEM3);
    cudaFuncSetAttribute(gemm_split<0,3,0>, cudaFuncAttributeMaxDynamicSharedMemorySize, SMEM3);
    cudaFuncSetAttribute(gemm_split<1,2,1>, cudaFuncAttributeMaxDynamicSharedMemorySize, SMEM2);

    // 0) split inputs (hs; 4 weights in one launch, wq/wk row-permuted)
    split_kernel<<<(unsigned)((NH / 4 + 255) / 256), 256>>>(hs, hsh, hsl, NH);
    dim3 gW((unsigned)((WN / 4 + 255) / 256), 4);
    split_w_kernel<<<gW, 256>>>(wq, wk, wv, wo, wh, wl);

    // 1) QKV merged + fused RoPE epilogue
    dim3 gQKV(HH / 128, NR / 128, 3);
    gemm_split<3,3,0><<<gQKV, 256, SMEM3>>>(hsh, hsl, wh, wl,
                                            out_v, out_krot, qkh, qkl,
                                            fcos, fsin, NR, HH, HH, 0, WN, 0, 1.f);

    // 2) scores = 0.125 * Qr Kr^T  (batched)
    dim3 gS(SS / 128, SS / 128, BB);
    gemm_split<0,3,0><<<gS, 256, SMEM3>>>(qkh, qkl, qkh + NH, qkl + NH, sc, nullptr,
                                          nullptr, nullptr, nullptr, nullptr, SS, SS, HH,
                                          (long)SS * HH, (long)SS * HH, (long)SS * SS, ATT_SCALE);

    // 3) softmax -> single fp16 P
    softmax_fp16_kernel<<<NR, 256>>>(sc, p16);

    // 4) V transpose + fp16 split
    dim3 gT(SS / 32, HH / 32, BB);
    transpose_split16_kernel<<<gT, dim3(32, 8)>>>(out_v, vth, vtl);

    // 5) ctx = P16 @ V16^T (2-term fp16) -> split epilogue to cx hi/lo (bf16)
    dim3 gC(HH / 128, SS / 128, BB);
    gemm_split<1,2,1><<<gC, 256, SMEM2>>>((const __nv_bfloat16*)p16, nullptr,
                                          (const __nv_bfloat16*)vth, (const __nv_bfloat16*)vtl,
                                          nullptr, nullptr, cxh, cxl, nullptr, nullptr,
                                          SS, HH, SS,
                                          (long)SS * SS, (long)HH * SS, (long)SS * HH, 1.f);

    // 6) output projection (bf16 x3)
    dim3 gO(HH / 128, NR / 128, 1);
    gemm_split<0,3,0><<<gO, 256, SMEM3>>>(cxh, cxl, wh + 3 * WN, wl + 3 * WN, out, nullptr,
                                          nullptr, nullptr, nullptr, nullptr,
                                          NR, HH, HH, 0, 0, 0, 1.f);
}